// round 5
// baseline (speedup 1.0000x reference)
#include <cuda_runtime.h>
#include <cuda_bf16.h>
#include <math.h>
#include <float.h>
#include <stdint.h>

// Problem constants
#define Bc    2
#define Sc    1024
#define HIDc  2048
#define NHc   16
#define HDc   128
#define SBc   20
#define RBc   82
#define CBc   163
#define FFc   0.9f
#define BSc   (Bc*Sc)          // 2048
#define ZB    (Bc*NHc)         // 32
#define NELT  (BSc*HIDc)       // 4M

// ----------------------------------------------------------------------------
// Scratch
// ----------------------------------------------------------------------------
__device__ __align__(1024) float g_lin[3*NELT];                  // Q,K,V linear
__device__ __align__(1024) __nv_bfloat16 g_hsH[NELT];
__device__ __align__(1024) __nv_bfloat16 g_hsL[NELT];
__device__ __align__(1024) __nv_bfloat16 g_wH[4*HIDc*HIDc];      // wq,wk,wv,wo
__device__ __align__(1024) __nv_bfloat16 g_wL[4*HIDc*HIDc];
__device__ __align__(1024) __nv_bfloat16 g_QH[ZB*Sc*HDc];
__device__ __align__(1024) __nv_bfloat16 g_QL[ZB*Sc*HDc];
__device__ __align__(1024) __nv_bfloat16 g_KH[ZB*Sc*HDc];
__device__ __align__(1024) __nv_bfloat16 g_KL[ZB*Sc*HDc];
__device__ __align__(1024) __nv_bfloat16 g_VH[ZB*Sc*HDc];
__device__ __align__(1024) __nv_bfloat16 g_VL[ZB*Sc*HDc];
__device__ __align__(1024) float g_P[(size_t)ZB*Sc*Sc];
__device__ __align__(1024) __nv_bfloat16 g_PH[(size_t)ZB*Sc*Sc];
__device__ __align__(1024) __nv_bfloat16 g_PL[(size_t)ZB*Sc*Sc];
__device__ __align__(1024) __nv_bfloat16 g_cH[NELT];
__device__ __align__(1024) __nv_bfloat16 g_cL[NELT];
__device__ int g_evict[ZB*Sc];
__device__ float g_tcos[Sc*64];
__device__ float g_tsin[Sc*64];

// ----------------------------------------------------------------------------
// PTX helpers
// ----------------------------------------------------------------------------
__device__ __forceinline__ uint32_t smem_u32(const void* p){
    uint32_t a;
    asm("{ .reg .u64 t; cvta.to.shared.u64 t, %1; cvt.u32.u64 %0, t; }":"=r"(a):"l"(p));
    return a;
}
__device__ __forceinline__ void cp16(uint32_t d, const void* s){
    asm volatile("cp.async.cg.shared.global [%0], [%1], 16;"::"r"(d),"l"(s));
}
#define CP_COMMIT() asm volatile("cp.async.commit_group;":::"memory")
#define CP_WAIT(n)  asm volatile("cp.async.wait_group %0;"::"n"(n):"memory")

__device__ __forceinline__ void ldsm4(uint32_t r[4], uint32_t a){
    asm volatile("ldmatrix.sync.aligned.m8n8.x4.shared.b16 {%0,%1,%2,%3}, [%4];"
        : "=r"(r[0]),"=r"(r[1]),"=r"(r[2]),"=r"(r[3]) : "r"(a));
}
__device__ __forceinline__ void ldsm4t(uint32_t r[4], uint32_t a){
    asm volatile("ldmatrix.sync.aligned.m8n8.x4.trans.shared.b16 {%0,%1,%2,%3}, [%4];"
        : "=r"(r[0]),"=r"(r[1]),"=r"(r[2]),"=r"(r[3]) : "r"(a));
}
__device__ __forceinline__ void mma16816(float d[4], const uint32_t a[4], const uint32_t b[2]){
    asm volatile("mma.sync.aligned.m16n8k16.row.col.f32.bf16.bf16.f32 "
        "{%0,%1,%2,%3},{%4,%5,%6,%7},{%8,%9},{%0,%1,%2,%3};"
        : "+f"(d[0]),"+f"(d[1]),"+f"(d[2]),"+f"(d[3])
        : "r"(a[0]),"r"(a[1]),"r"(a[2]),"r"(a[3]),"r"(b[0]),"r"(b[1]));
}

// K-chunk 32 config: tiles are 8 KB each, stage = 4 tiles = 32 KB, 3 stages.
#define TILE32      8192
#define STAGE_BYTES 32768
#define NSTAGE      3
#define GSMEM_TOTAL (NSTAGE*STAGE_BYTES)   // 96 KB -> 2 CTAs/SM

// [128 rows x 32 bf16] tile: 2 rows packed per 128B line.
// addr(r, kq) = (r>>1)*128 + ((((r&1)<<2)|kq) ^ ((r>>1)&7))*16, kq in 0..3
__device__ __forceinline__ uint32_t a32_addr(uint32_t r, uint32_t kq){
    uint32_t line = r>>1;
    uint32_t ci = ((r&1)<<2) | kq;
    return line*128u + ((ci ^ (line&7u))<<4);
}
__device__ __forceinline__ void copy_a32(uint32_t dst, const __nv_bfloat16* src,
                                         int ld, int tid){
#pragma unroll
    for (int i=0;i<2;i++){
        int idx = tid*2 + i;              // 0..511
        uint32_t r = (uint32_t)(idx>>2), kq = (uint32_t)(idx&3);
        cp16(dst + a32_addr(r,kq), (const char*)src + ((long long)r*ld + kq*8)*2);
    }
}
// [32 rows(k) x 128 bf16(n)] tile, rowbytes=256, XOR-(r&7) chunk swizzle.
__device__ __forceinline__ void copy_kn32(uint32_t dst, const __nv_bfloat16* src,
                                          int ld, int tid){
#pragma unroll
    for (int i=0;i<2;i++){
        int idx = tid*2 + i;              // 0..511
        uint32_t r = (uint32_t)(idx>>4), c = (uint32_t)(idx&15);
        uint32_t sw = r*256u + (((c ^ (r&7u)))<<4);
        cp16(dst + sw, (const char*)src + ((long long)r*ld + c*8)*2);
    }
}

// ----------------------------------------------------------------------------
// HMMA GEMM: C[M,N] = alpha * (Ah+Al)[M,K] @ (Bh+Bl)^T, fp32 acc, 3-term split.
// BKN=true : B stored [K,N] row-major (trans ldmatrix)
// BKN=false: B stored [N,K] row-major
// CAUSAL: skip 128x128 blocks strictly above the diagonal.
// SPLITOUT: write bf16 hi/lo (CH/CL) instead of fp32 C.
// CTA 128x128, 8 warps (2x4 of 64x32), K-chunk 32, 3-stage cp.async, 2 CTA/SM.
// ----------------------------------------------------------------------------
template<bool BKN, bool CAUSAL, bool SPLITOUT>
__global__ void __launch_bounds__(256,2) gemm_mma(
    const __nv_bfloat16* __restrict__ Ah, const __nv_bfloat16* __restrict__ Al,
    const __nv_bfloat16* __restrict__ Bh, const __nv_bfloat16* __restrict__ Bl,
    float* __restrict__ C,
    __nv_bfloat16* __restrict__ CH, __nv_bfloat16* __restrict__ CL,
    int K, int ldb, int ldc,
    long long sA, long long sB, long long sCo, long long sCi, int ndiv, float alpha)
{
    const int m0 = blockIdx.y*128, n0 = blockIdx.x*128, z = blockIdx.z;
    if (CAUSAL && n0 > m0) return;
    extern __shared__ __align__(1024) char smem[];
    const uint32_t sb = smem_u32(smem);
    Ah += (long long)z*sA; Al += (long long)z*sA;
    Bh += (long long)z*sB; Bl += (long long)z*sB;
    long long coff = (long long)(z/ndiv)*sCo + (long long)(z%ndiv)*sCi;
    if (SPLITOUT){ CH += coff; CL += coff; } else { C += coff; }

    const int tid = threadIdx.x, lane = tid&31, wid = tid>>5;
    const int wm = wid>>2, wn = wid&3;

    float acc[4][4][4];
#pragma unroll
    for (int a=0;a<4;a++)
#pragma unroll
        for (int b=0;b<4;b++)
#pragma unroll
            for (int c=0;c<4;c++) acc[a][b][c] = 0.f;

    const int nch = K>>5;

#define LOAD_CHUNK(cc, ss) do{ \
    uint32_t bbase = sb + (uint32_t)(ss)*STAGE_BYTES; \
    copy_a32(bbase,           Ah + (long long)m0*K + (cc)*32, K, tid); \
    copy_a32(bbase + TILE32,  Al + (long long)m0*K + (cc)*32, K, tid); \
    if (BKN){ \
        copy_kn32(bbase + 2*TILE32, Bh + (long long)(cc)*32*ldb + n0, ldb, tid); \
        copy_kn32(bbase + 3*TILE32, Bl + (long long)(cc)*32*ldb + n0, ldb, tid); \
    } else { \
        copy_a32(bbase + 2*TILE32, Bh + (long long)n0*K + (cc)*32, K, tid); \
        copy_a32(bbase + 3*TILE32, Bl + (long long)n0*K + (cc)*32, K, tid); \
    } \
    CP_COMMIT(); }while(0)

    LOAD_CHUNK(0, 0);
    if (nch > 1) LOAD_CHUNK(1, 1);
    if (nch > 2) LOAD_CHUNK(2, 2);

    const uint32_t axor = (uint32_t)(lane&7);

    for (int c=0; c<nch; c++){
        int pend = nch-1-c; if (pend > NSTAGE-1) pend = NSTAGE-1;
        if (pend >= 2) CP_WAIT(2);
        else if (pend == 1) CP_WAIT(1);
        else CP_WAIT(0);
        __syncthreads();
        uint32_t base = sb + (uint32_t)(c % NSTAGE)*STAGE_BYTES;
#pragma unroll
        for (int ks=0; ks<2; ks++){
            uint32_t ah[4][4], al[4][4], bh[4][2], bl[4][2];
#pragma unroll
            for (int mb=0;mb<4;mb++){
                uint32_t row = (uint32_t)(wm*64 + mb*16 + (lane&15));
                uint32_t kq  = (uint32_t)(ks*2 + (lane>>4));
                uint32_t ad = base + a32_addr(row, kq);
                ldsm4(ah[mb], ad);
                ldsm4(al[mb], ad + TILE32);
            }
#pragma unroll
            for (int nb=0;nb<2;nb++){
                uint32_t t[4];
                if (BKN){
                    uint32_t row = (uint32_t)(ks*16 + (lane&7) + (((lane>>3)&1)<<3));
                    uint32_t ch  = ((uint32_t)(wn*4 + nb*2 + (lane>>4)) ^ axor);
                    uint32_t ad  = base + 2*TILE32 + row*256 + (ch<<4);
                    ldsm4t(t, ad);
                    bh[2*nb][0]=t[0]; bh[2*nb][1]=t[1]; bh[2*nb+1][0]=t[2]; bh[2*nb+1][1]=t[3];
                    ldsm4t(t, ad + TILE32);
                    bl[2*nb][0]=t[0]; bl[2*nb][1]=t[1]; bl[2*nb+1][0]=t[2]; bl[2*nb+1][1]=t[3];
                } else {
                    uint32_t row = (uint32_t)(wn*32 + nb*16 + (lane&7) + ((lane>>4)<<3));
                    uint32_t kq  = (uint32_t)(ks*2 + ((lane>>3)&1));
                    uint32_t ad  = base + 2*TILE32 + a32_addr(row, kq);
                    ldsm4(t, ad);
                    bh[2*nb][0]=t[0]; bh[2*nb][1]=t[1]; bh[2*nb+1][0]=t[2]; bh[2*nb+1][1]=t[3];
                    ldsm4(t, ad + TILE32);
                    bl[2*nb][0]=t[0]; bl[2*nb][1]=t[1]; bl[2*nb+1][0]=t[2]; bl[2*nb+1][1]=t[3];
                }
            }
#pragma unroll
            for (int mb=0;mb<4;mb++)
#pragma unroll
                for (int n8=0;n8<4;n8++){
                    mma16816(acc[mb][n8], ah[mb], bh[n8]);
                    mma16816(acc[mb][n8], ah[mb], bl[n8]);
                    mma16816(acc[mb][n8], al[mb], bh[n8]);
                }
        }
        __syncthreads();
        if (c + NSTAGE < nch) LOAD_CHUNK(c + NSTAGE, c % NSTAGE);
    }
#undef LOAD_CHUNK

    // epilogue
#pragma unroll
    for (int mb=0;mb<4;mb++){
        int r0 = m0 + wm*64 + mb*16 + (lane>>2);
#pragma unroll
        for (int n8=0;n8<4;n8++){
            int cc = n0 + wn*32 + n8*8 + (lane&3)*2;
            float vx0 = acc[mb][n8][0]*alpha, vy0 = acc[mb][n8][1]*alpha;
            float vx1 = acc[mb][n8][2]*alpha, vy1 = acc[mb][n8][3]*alpha;
            if (SPLITOUT){
                __nv_bfloat162 h0, l0, h1, l1;
                h0.x = __float2bfloat16(vx0); h0.y = __float2bfloat16(vy0);
                l0.x = __float2bfloat16(vx0 - __bfloat162float(h0.x));
                l0.y = __float2bfloat16(vy0 - __bfloat162float(h0.y));
                h1.x = __float2bfloat16(vx1); h1.y = __float2bfloat16(vy1);
                l1.x = __float2bfloat16(vx1 - __bfloat162float(h1.x));
                l1.y = __float2bfloat16(vy1 - __bfloat162float(h1.y));
                *(__nv_bfloat162*)&CH[(long long)r0*ldc + cc] = h0;
                *(__nv_bfloat162*)&CL[(long long)r0*ldc + cc] = l0;
                *(__nv_bfloat162*)&CH[(long long)(r0+8)*ldc + cc] = h1;
                *(__nv_bfloat162*)&CL[(long long)(r0+8)*ldc + cc] = l1;
            } else {
                float2 v0; v0.x = vx0; v0.y = vy0;
                float2 v1; v1.x = vx1; v1.y = vy1;
                *(float2*)&C[(long long)r0*ldc + cc] = v0;
                *(float2*)&C[(long long)(r0+8)*ldc + cc] = v1;
            }
        }
    }
}

// ----------------------------------------------------------------------------
// fp32 -> bf16 hi/lo split
// ----------------------------------------------------------------------------
__global__ void split_plain(const float* __restrict__ X,
                            __nv_bfloat16* __restrict__ H,
                            __nv_bfloat16* __restrict__ L, int n)
{
    int i = (blockIdx.x*blockDim.x + threadIdx.x)*4;
    if (i < n){
        float4 v = *(const float4*)&X[i];
        __nv_bfloat16 h0=__float2bfloat16(v.x), h1=__float2bfloat16(v.y);
        __nv_bfloat16 h2=__float2bfloat16(v.z), h3=__float2bfloat16(v.w);
        __nv_bfloat162 H01; H01.x=h0; H01.y=h1;
        __nv_bfloat162 H23; H23.x=h2; H23.y=h3;
        *(__nv_bfloat162*)&H[i]   = H01;
        *(__nv_bfloat162*)&H[i+2] = H23;
        __nv_bfloat162 L01, L23;
        L01.x = __float2bfloat16(v.x - __bfloat162float(h0));
        L01.y = __float2bfloat16(v.y - __bfloat162float(h1));
        L23.x = __float2bfloat16(v.z - __bfloat162float(h2));
        L23.y = __float2bfloat16(v.w - __bfloat162float(h3));
        *(__nv_bfloat162*)&L[i]   = L01;
        *(__nv_bfloat162*)&L[i+2] = L23;
    }
}

// ----------------------------------------------------------------------------
// RoPE cos/sin tables
// ----------------------------------------------------------------------------
__global__ void rope_tables()
{
    int idx = blockIdx.x*blockDim.x + threadIdx.x;   // 0 .. Sc*64-1
    int s = idx >> 6, i = idx & 63;
    double inv = pow(10000.0, -(double)i/64.0);
    double a = (double)s * inv;
    g_tcos[idx] = (float)cos(a);
    g_tsin[idx] = (float)sin(a);
}

// ----------------------------------------------------------------------------
// RoPE + [B,S,H*D]->[Z,S,D] layout + bf16 hi/lo split (reads g_lin Q/K/V)
// ----------------------------------------------------------------------------
__global__ void rope_split()
{
    long long idx = (long long)blockIdx.x * blockDim.x + threadIdx.x;
    if (idx >= (long long)NELT) return;

    int d = (int)(idx % HDc);
    int h = (int)((idx / HDc) % NHc);
    int s = (int)((idx / HIDc) % Sc);
    int b = (int)(idx / ((long long)Sc * HIDc));
    int z = b*NHc + h;

    long long lin = (long long)(b * Sc + s) * HIDc + h * HDc + d;
    long long out = (long long)(z * Sc + s) * HDc + d;

    const float* Qlin = g_lin;
    const float* Klin = g_lin + NELT;
    const float* Vlin = g_lin + 2*(long long)NELT;

    float q = Qlin[lin];
    float k = Klin[lin];
    float qr, kr;
    if (d < 64) { qr = -Qlin[lin + 64]; kr = -Klin[lin + 64]; }
    else        { qr =  Qlin[lin - 64]; kr =  Klin[lin - 64]; }

    int ti = (s<<6) + (d & 63);
    float c = g_tcos[ti], sn = g_tsin[ti];

    float qv = q * c + qr * sn;
    float kv = k * c + kr * sn;

    __nv_bfloat16 qh = __float2bfloat16(qv);
    g_QH[out] = qh; g_QL[out] = __float2bfloat16(qv - __bfloat162float(qh));
    __nv_bfloat16 kh = __float2bfloat16(kv);
    g_KH[out] = kh; g_KL[out] = __float2bfloat16(kv - __bfloat162float(kh));

    float vv = Vlin[lin];
    __nv_bfloat16 vh = __float2bfloat16(vv);
    g_VH[out] = vh; g_VL[out] = __float2bfloat16(vv - __bfloat162float(vh));
}

// ----------------------------------------------------------------------------
// Causal row softmax
// ----------------------------------------------------------------------------
__global__ void __launch_bounds__(256) softmax_causal(float* __restrict__ P)
{
    __shared__ float smA[9];
    __shared__ float smB[9];
    long long row = blockIdx.x;
    int r = (int)(row & (Sc-1));
    float* p = P + row * Sc;
    const int tid = threadIdx.x;
    const int lane = tid & 31, wid = tid >> 5;

    float v[4];
    float mx = -FLT_MAX;
#pragma unroll
    for (int i = 0; i < 4; i++) {
        int jj = tid + i*256;
        v[i] = (jj <= r) ? p[jj] : -FLT_MAX;
        mx = fmaxf(mx, v[i]);
    }
#pragma unroll
    for (int o = 16; o; o >>= 1) mx = fmaxf(mx, __shfl_xor_sync(0xffffffffu, mx, o));
    if (lane == 0) smA[wid] = mx;
    __syncthreads();
    if (tid < 8) {
        float x = smA[tid];
#pragma unroll
        for (int o = 4; o; o >>= 1) x = fmaxf(x, __shfl_xor_sync(0xffu, x, o));
        if (tid == 0) smA[8] = x;
    }
    __syncthreads();
    mx = smA[8];

    float sum = 0.f;
#pragma unroll
    for (int i = 0; i < 4; i++) { v[i] = expf(v[i] - mx); sum += v[i]; }
#pragma unroll
    for (int o = 16; o; o >>= 1) sum += __shfl_xor_sync(0xffffffffu, sum, o);
    if (lane == 0) smB[wid] = sum;
    __syncthreads();
    if (tid < 8) {
        float x = smB[tid];
#pragma unroll
        for (int o = 4; o; o >>= 1) x += __shfl_xor_sync(0xffu, x, o);
        if (tid == 0) smB[8] = x;
    }
    __syncthreads();
    sum = smB[8];

    float inv = 1.f / sum;
#pragma unroll
    for (int i = 0; i < 4; i++) p[tid + i * 256] = v[i] * inv;
}

// ----------------------------------------------------------------------------
// Sequential heavy-hitter eviction scan (2 barriers/step + prefetch)
// ----------------------------------------------------------------------------
__global__ void __launch_bounds__(1024) scan_kernel(const float* __restrict__ P,
                                                    int* __restrict__ evict)
{
    const int z = blockIdx.x;
    const float* Pz = P + (long long)z * Sc * Sc;
    const int j = threadIdx.x;
    const int lane = j & 31, wid = j >> 5;

    __shared__ float wcoef[CBc];
    __shared__ float sred[32];
    __shared__ unsigned long long mred[32];

    if (j < CBc) wcoef[j] = powf(FFc, (float)(CBc - 1 - j));
    __syncthreads();

    float sel = 0.f;
    for (int i = 0; i < CBc; i++)
        sel += wcoef[i] * Pz[(long long)i * Sc + j];

    const float INFV = __int_as_float(0x7f800000);
    int my_e = 0x7fffffff;

    float sc = __ldg(&Pz[(long long)CBc * Sc + j]);

    for (int t = CBc; t <= Sc - 2; t++) {
        float nxt = 0.f;
        if (t < Sc - 2) nxt = __ldg(&Pz[(long long)(t+1) * Sc + j]);

        bool alive = (sel < INFV);
        float cur = alive ? sc : 0.f;

        float x = cur;
#pragma unroll
        for (int o = 16; o; o >>= 1) x += __shfl_xor_sync(0xffffffffu, x, o);
        if (lane == 0) sred[wid] = x;
        __syncthreads();
        float y = sred[lane];
#pragma unroll
        for (int o = 16; o; o >>= 1) y += __shfl_xor_sync(0xffffffffu, y, o);
        float total = y;

        sel = alive ? (FFc * sel + cur / total) : INFV;

        unsigned long long key = ~0ull;
        if (j >= SBc && j <= t - RBc)
            key = (((unsigned long long)__float_as_uint(sel)) << 32) | (unsigned)j;
#pragma unroll
        for (int o = 16; o; o >>= 1) {
            unsigned long long other = __shfl_xor_sync(0xffffffffu, key, o);
            key = (other < key) ? other : key;
        }
        if (lane == 0) mred[wid] = key;
        __syncthreads();
        unsigned long long y2 = mred[lane];
#pragma unroll
        for (int o = 16; o; o >>= 1) {
            unsigned long long other = __shfl_xor_sync(0xffffffffu, y2, o);
            y2 = (other < y2) ? other : y2;
        }
        int mi = (int)(y2 & 0xffffffffu);
        if (j == mi) { sel = INFV; my_e = t; }

        sc = nxt;
    }

    evict[z * Sc + j] = my_e;
}

// ----------------------------------------------------------------------------
// Keep-mask + renormalize; emit bf16 hi/lo splits
// ----------------------------------------------------------------------------
__global__ void __launch_bounds__(256) maskrenorm_split(const float* __restrict__ P,
                                                        const int* __restrict__ evict,
                                                        __nv_bfloat16* __restrict__ PH,
                                                        __nv_bfloat16* __restrict__ PL)
{
    __shared__ float smB[9];
    long long row = blockIdx.x;
    int z = (int)(row >> 10);
    int r = (int)(row & 1023);
    const float* p = P + row * Sc;
    const int* e = evict + z * Sc;
    const int tid = threadIdx.x;
    const int lane = tid & 31, wid = tid >> 5;

    float v[4];
    float sum = 0.f;
#pragma unroll
    for (int i = 0; i < 4; i++) {
        int jj = tid + i * 256;
        bool keep = (r <= CBc) || (e[jj] >= r);
        v[i] = keep ? p[jj] : 0.f;
        sum += v[i];
    }
#pragma unroll
    for (int o = 16; o; o >>= 1) sum += __shfl_xor_sync(0xffffffffu, sum, o);
    if (lane == 0) smB[wid] = sum;
    __syncthreads();
    if (tid < 8) {
        float x = smB[tid];
#pragma unroll
        for (int o = 4; o; o >>= 1) x += __shfl_xor_sync(0xffu, x, o);
        if (tid == 0) smB[8] = x;
    }
    __syncthreads();
    sum = smB[8];

    float inv = 1.f / sum;
    long long base = row * Sc;
#pragma unroll
    for (int i = 0; i < 4; i++) {
        int jj = tid + i * 256;
        float val = v[i] * inv;
        __nv_bfloat16 h = __float2bfloat16(val);
        PH[base + jj] = h;
        PL[base + jj] = __float2bfloat16(val - __bfloat162float(h));
    }
}

// ----------------------------------------------------------------------------
// Launch
// ----------------------------------------------------------------------------
extern "C" void kernel_launch(void* const* d_in, const int* in_sizes, int n_in,
                              void* d_out, int out_size)
{
    (void)in_sizes; (void)n_in; (void)out_size;
    const float* hs = (const float*)d_in[0];
    const float* wq = (const float*)d_in[1];
    const float* wk = (const float*)d_in[2];
    const float* wv = (const float*)d_in[3];
    const float* wo = (const float*)d_in[4];
    float* out = (float*)d_out;

    float *lin, *P;
    __nv_bfloat16 *hsH, *hsL, *wH, *wL;
    __nv_bfloat16 *QH, *QL, *KH, *KL, *VH, *VL, *PH, *PL, *cH, *cL;
    int* ev;
    cudaGetSymbolAddress((void**)&lin, g_lin);
    cudaGetSymbolAddress((void**)&hsH, g_hsH);  cudaGetSymbolAddress((void**)&hsL, g_hsL);
    cudaGetSymbolAddress((void**)&wH, g_wH);    cudaGetSymbolAddress((void**)&wL, g_wL);
    cudaGetSymbolAddress((void**)&QH, g_QH);    cudaGetSymbolAddress((void**)&QL, g_QL);
    cudaGetSymbolAddress((void**)&KH, g_KH);    cudaGetSymbolAddress((void**)&KL, g_KL);
    cudaGetSymbolAddress((void**)&VH, g_VH);    cudaGetSymbolAddress((void**)&VL, g_VL);
    cudaGetSymbolAddress((void**)&P, g_P);
    cudaGetSymbolAddress((void**)&PH, g_PH);    cudaGetSymbolAddress((void**)&PL, g_PL);
    cudaGetSymbolAddress((void**)&cH, g_cH);    cudaGetSymbolAddress((void**)&cL, g_cL);
    cudaGetSymbolAddress((void**)&ev, g_evict);

    cudaFuncSetAttribute(gemm_mma<true,false,false>,  cudaFuncAttributeMaxDynamicSharedMemorySize, GSMEM_TOTAL);
    cudaFuncSetAttribute(gemm_mma<false,true,false>,  cudaFuncAttributeMaxDynamicSharedMemorySize, GSMEM_TOTAL);
    cudaFuncSetAttribute(gemm_mma<true,false,true>,   cudaFuncAttributeMaxDynamicSharedMemorySize, GSMEM_TOTAL);

    const float qk_scale = 0.08838834764831845f;  // 1/sqrt(128)
    const int splitBlocks = NELT/4/256;

    // 0) RoPE tables
    rope_tables<<<(Sc*64)/256, 256>>>();

    // 1) bf16 hi/lo splits (weights into one contiguous buffer: q,k,v,o)
    split_plain<<<splitBlocks, 256>>>(hs, hsH, hsL, NELT);
    split_plain<<<splitBlocks, 256>>>(wq, wH + 0*(size_t)HIDc*HIDc, wL + 0*(size_t)HIDc*HIDc, NELT);
    split_plain<<<splitBlocks, 256>>>(wk, wH + 1*(size_t)HIDc*HIDc, wL + 1*(size_t)HIDc*HIDc, NELT);
    split_plain<<<splitBlocks, 256>>>(wv, wH + 2*(size_t)HIDc*HIDc, wL + 2*(size_t)HIDc*HIDc, NELT);
    split_plain<<<splitBlocks, 256>>>(wo, wH + 3*(size_t)HIDc*HIDc, wL + 3*(size_t)HIDc*HIDc, NELT);

    // 2) Fused QKV projections: grid.z selects weight + output slice
    gemm_mma<true,false,false><<<dim3(16,16,3), 256, GSMEM_TOTAL>>>(hsH, hsL, wH, wL, lin,
        nullptr, nullptr, HIDc, HIDc, HIDc,
        0, (long long)HIDc*HIDc, (long long)NELT, 0, 1, 1.f);

    // 3) RoPE + layout + split
    rope_split<<<NELT/256, 256>>>();

    // 4) QK^T causal, scaled
    gemm_mma<false,true,false><<<dim3(8,8,ZB), 256, GSMEM_TOTAL>>>(QH, QL, KH, KL, P,
        nullptr, nullptr, HDc, HDc, Sc,
        (long long)Sc*HDc, (long long)Sc*HDc,
        (long long)Sc*Sc, 0, 1, qk_scale);

    // 5) softmax
    softmax_causal<<<ZB*Sc, 256>>>(P);

    // 6) eviction scan
    scan_kernel<<<ZB, 1024>>>(P, ev);

    // 7) mask + renormalize -> bf16 splits
    maskrenorm_split<<<ZB*Sc, 256>>>(P, ev, PH, PL);

    // 8) PV -> ctx (bf16 hi/lo direct)
    gemm_mma<true,false,true><<<dim3(1,8,ZB), 256, GSMEM_TOTAL>>>(PH, PL, VH, VL,
        nullptr, cH, cL, Sc, HDc, HIDc,
        (long long)Sc*Sc, (long long)Sc*HDc,
        (long long)Sc*HIDc, (long long)HDc, NHc, 1.f);

    // 9) output projection
    gemm_mma<true,false,false><<<dim3(16,16,1), 256, GSMEM_TOTAL>>>(cH, cL,
        wH + 3*(size_t)HIDc*HIDc, wL + 3*(size_t)HIDc*HIDc, out,
        nullptr, nullptr, HIDc, HIDc, HIDc, 0, 0, 0, 0, 1, 1.f);
}

// round 6
// speedup vs baseline: 1.0123x; 1.0123x over previous
#include <cuda_runtime.h>
#include <cuda_bf16.h>
#include <math.h>
#include <float.h>
#include <stdint.h>

// Problem constants
#define Bc    2
#define Sc    1024
#define HIDc  2048
#define NHc   16
#define HDc   128
#define SBc   20
#define RBc   82
#define CBc   163
#define FFc   0.9f
#define BSc   (Bc*Sc)          // 2048
#define ZB    (Bc*NHc)         // 32
#define NELT  (BSc*HIDc)       // 4M

// ----------------------------------------------------------------------------
// Scratch
// ----------------------------------------------------------------------------
__device__ __align__(1024) float g_lin[3*NELT];                  // Q,K,V linear
__device__ __align__(1024) __nv_bfloat16 g_hsH[NELT];
__device__ __align__(1024) __nv_bfloat16 g_hsL[NELT];
__device__ __align__(1024) __nv_bfloat16 g_wH[4*HIDc*HIDc];      // wq,wk,wv,wo
__device__ __align__(1024) __nv_bfloat16 g_wL[4*HIDc*HIDc];
__device__ __align__(1024) __nv_bfloat16 g_QH[ZB*Sc*HDc];
__device__ __align__(1024) __nv_bfloat16 g_QL[ZB*Sc*HDc];
__device__ __align__(1024) __nv_bfloat16 g_KH[ZB*Sc*HDc];
__device__ __align__(1024) __nv_bfloat16 g_KL[ZB*Sc*HDc];
__device__ __align__(1024) __nv_bfloat16 g_VH[ZB*Sc*HDc];
__device__ __align__(1024) __nv_bfloat16 g_VL[ZB*Sc*HDc];
__device__ __align__(1024) float g_P[(size_t)ZB*Sc*Sc];
__device__ __align__(1024) __nv_bfloat16 g_PH[(size_t)ZB*Sc*Sc];
__device__ __align__(1024) __nv_bfloat16 g_PL[(size_t)ZB*Sc*Sc];
__device__ __align__(1024) __nv_bfloat16 g_cH[NELT];
__device__ __align__(1024) __nv_bfloat16 g_cL[NELT];
__device__ int g_evict[ZB*Sc];
__device__ float g_tcos[Sc*64];
__device__ float g_tsin[Sc*64];

// ----------------------------------------------------------------------------
// PTX helpers
// ----------------------------------------------------------------------------
__device__ __forceinline__ uint32_t smem_u32(const void* p){
    uint32_t a;
    asm("{ .reg .u64 t; cvta.to.shared.u64 t, %1; cvt.u32.u64 %0, t; }":"=r"(a):"l"(p));
    return a;
}
__device__ __forceinline__ void cp16(uint32_t d, const void* s){
    asm volatile("cp.async.cg.shared.global [%0], [%1], 16;"::"r"(d),"l"(s));
}
#define CP_COMMIT() asm volatile("cp.async.commit_group;":::"memory")
#define CP_WAIT(n)  asm volatile("cp.async.wait_group %0;"::"n"(n):"memory")

__device__ __forceinline__ void ldsm4(uint32_t r[4], uint32_t a){
    asm volatile("ldmatrix.sync.aligned.m8n8.x4.shared.b16 {%0,%1,%2,%3}, [%4];"
        : "=r"(r[0]),"=r"(r[1]),"=r"(r[2]),"=r"(r[3]) : "r"(a));
}
__device__ __forceinline__ void ldsm4t(uint32_t r[4], uint32_t a){
    asm volatile("ldmatrix.sync.aligned.m8n8.x4.trans.shared.b16 {%0,%1,%2,%3}, [%4];"
        : "=r"(r[0]),"=r"(r[1]),"=r"(r[2]),"=r"(r[3]) : "r"(a));
}
__device__ __forceinline__ void mma16816(float d[4], const uint32_t a[4], const uint32_t b[2]){
    asm volatile("mma.sync.aligned.m16n8k16.row.col.f32.bf16.bf16.f32 "
        "{%0,%1,%2,%3},{%4,%5,%6,%7},{%8,%9},{%0,%1,%2,%3};"
        : "+f"(d[0]),"+f"(d[1]),"+f"(d[2]),"+f"(d[3])
        : "r"(a[0]),"r"(a[1]),"r"(a[2]),"r"(a[3]),"r"(b[0]),"r"(b[1]));
}

// K-chunk 64 config (R4-proven): tiles 16KB, stage = 4 tiles = 64KB, 3 stages.
#define TILEB       16384
#define STAGE_BYTES 65536
#define NSTAGE      3
#define GSMEM_TOTAL (NSTAGE*STAGE_BYTES)   // 192 KB

// Copy a [128 rows x 64 bf16] tile, rowbytes=128, XOR-(r&7) chunk swizzle.
// 512 threads: 2 cp16/thread.
__device__ __forceinline__ void copy_rk(uint32_t dst, const __nv_bfloat16* src,
                                        int ld, int tid){
#pragma unroll
    for (int i=0;i<2;i++){
        int idx = tid + i*512;            // 0..1023
        int r = idx>>3, c = idx&7;
        uint32_t sw = (uint32_t)(r*128) + (uint32_t)(((c ^ (r&7))<<4));
        cp16(dst + sw, (const char*)src + ((long long)r*ld + c*8)*2);
    }
}
// Copy a [64 rows(k) x 128 bf16(n)] tile, rowbytes=256, XOR-(r&7) chunk swizzle.
__device__ __forceinline__ void copy_kn(uint32_t dst, const __nv_bfloat16* src,
                                        int ld, int tid){
#pragma unroll
    for (int i=0;i<2;i++){
        int idx = tid + i*512;            // 0..1023
        int r = idx>>4, c = idx&15;
        uint32_t sw = (uint32_t)(r*256) + (uint32_t)(((c ^ (r&7))<<4));
        cp16(dst + sw, (const char*)src + ((long long)r*ld + c*8)*2);
    }
}

// ----------------------------------------------------------------------------
// HMMA GEMM: C[M,N] = alpha * (Ah+Al)[M,K] @ (Bh+Bl)^T, fp32 acc, 3-term split.
// BKN=true : B stored [K,N] row-major (trans ldmatrix)
// BKN=false: B stored [N,K] row-major
// CAUSAL: skip 128x128 blocks strictly above the diagonal.
// SPLITOUT: write bf16 hi/lo (CH/CL) instead of fp32 C.
// CTA 128x128, 16 warps (4x4 of 32x32) = 4 warps/SMSP for latency hiding.
// K-chunk 64, 3-stage cp.async pipeline, 192KB smem.
// ----------------------------------------------------------------------------
template<bool BKN, bool CAUSAL, bool SPLITOUT>
__global__ void __launch_bounds__(512) gemm_mma(
    const __nv_bfloat16* __restrict__ Ah, const __nv_bfloat16* __restrict__ Al,
    const __nv_bfloat16* __restrict__ Bh, const __nv_bfloat16* __restrict__ Bl,
    float* __restrict__ C,
    __nv_bfloat16* __restrict__ CH, __nv_bfloat16* __restrict__ CL,
    int K, int ldb, int ldc,
    long long sA, long long sB, long long sCo, long long sCi, int ndiv, float alpha)
{
    const int m0 = blockIdx.y*128, n0 = blockIdx.x*128, z = blockIdx.z;
    if (CAUSAL && n0 > m0) return;
    extern __shared__ __align__(1024) char smem[];
    const uint32_t sb = smem_u32(smem);
    Ah += (long long)z*sA; Al += (long long)z*sA;
    Bh += (long long)z*sB; Bl += (long long)z*sB;
    long long coff = (long long)(z/ndiv)*sCo + (long long)(z%ndiv)*sCi;
    if (SPLITOUT){ CH += coff; CL += coff; } else { C += coff; }

    const int tid = threadIdx.x, lane = tid&31, wid = tid>>5;
    const int wm = wid>>2, wn = wid&3;     // 4x4 warp grid, 32x32 warp tiles

    float acc[2][4][4];
#pragma unroll
    for (int a=0;a<2;a++)
#pragma unroll
        for (int b=0;b<4;b++)
#pragma unroll
            for (int c=0;c<4;c++) acc[a][b][c] = 0.f;

    const int nch = K>>6;

#define LOAD_CHUNK(cc, ss) do{ \
    uint32_t bbase = sb + (uint32_t)(ss)*STAGE_BYTES; \
    copy_rk(bbase,           Ah + (long long)m0*K + (cc)*64, K, tid); \
    copy_rk(bbase + TILEB,   Al + (long long)m0*K + (cc)*64, K, tid); \
    if (BKN){ \
        copy_kn(bbase + 2*TILEB, Bh + (long long)(cc)*64*ldb + n0, ldb, tid); \
        copy_kn(bbase + 3*TILEB, Bl + (long long)(cc)*64*ldb + n0, ldb, tid); \
    } else { \
        copy_rk(bbase + 2*TILEB, Bh + (long long)n0*K + (cc)*64, K, tid); \
        copy_rk(bbase + 3*TILEB, Bl + (long long)n0*K + (cc)*64, K, tid); \
    } \
    CP_COMMIT(); }while(0)

    LOAD_CHUNK(0, 0);
    if (nch > 1) LOAD_CHUNK(1, 1);
    if (nch > 2) LOAD_CHUNK(2, 2);

    const uint32_t axor = (uint32_t)(lane&7);

    for (int c=0; c<nch; c++){
        int pend = nch-1-c; if (pend > NSTAGE-1) pend = NSTAGE-1;
        if (pend >= 2) CP_WAIT(2);
        else if (pend == 1) CP_WAIT(1);
        else CP_WAIT(0);
        __syncthreads();
        uint32_t base = sb + (uint32_t)(c % NSTAGE)*STAGE_BYTES;
#pragma unroll
        for (int ks=0; ks<4; ks++){
            uint32_t ah[2][4], al[2][4], bh[4][2], bl[4][2];
#pragma unroll
            for (int mb=0;mb<2;mb++){
                uint32_t row = (uint32_t)(wm*32 + mb*16 + (lane&15));
                uint32_t col = (((uint32_t)(ks*2 + (lane>>4)) ^ (row&7u))<<4);
                uint32_t ad = base + row*128 + col;
                ldsm4(ah[mb], ad);
                ldsm4(al[mb], ad + TILEB);
            }
#pragma unroll
            for (int nb=0;nb<2;nb++){
                uint32_t t[4];
                if (BKN){
                    uint32_t row = (uint32_t)(ks*16 + (lane&7) + (((lane>>3)&1)<<3));
                    uint32_t ch  = ((uint32_t)(wn*4 + nb*2 + (lane>>4)) ^ axor);
                    uint32_t ad  = base + 2*TILEB + row*256 + (ch<<4);
                    ldsm4t(t, ad);
                    bh[2*nb][0]=t[0]; bh[2*nb][1]=t[1]; bh[2*nb+1][0]=t[2]; bh[2*nb+1][1]=t[3];
                    ldsm4t(t, ad + TILEB);
                    bl[2*nb][0]=t[0]; bl[2*nb][1]=t[1]; bl[2*nb+1][0]=t[2]; bl[2*nb+1][1]=t[3];
                } else {
                    uint32_t row = (uint32_t)(wn*32 + nb*16 + (lane&7) + ((lane>>4)<<3));
                    uint32_t ch  = ((uint32_t)(ks*2 + ((lane>>3)&1)) ^ (row&7u));
                    uint32_t ad  = base + 2*TILEB + row*128 + (ch<<4);
                    ldsm4(t, ad);
                    bh[2*nb][0]=t[0]; bh[2*nb][1]=t[1]; bh[2*nb+1][0]=t[2]; bh[2*nb+1][1]=t[3];
                    ldsm4(t, ad + TILEB);
                    bl[2*nb][0]=t[0]; bl[2*nb][1]=t[1]; bl[2*nb+1][0]=t[2]; bl[2*nb+1][1]=t[3];
                }
            }
#pragma unroll
            for (int mb=0;mb<2;mb++)
#pragma unroll
                for (int n8=0;n8<4;n8++){
                    mma16816(acc[mb][n8], ah[mb], bh[n8]);
                    mma16816(acc[mb][n8], ah[mb], bl[n8]);
                    mma16816(acc[mb][n8], al[mb], bh[n8]);
                }
        }
        __syncthreads();
        if (c + NSTAGE < nch) LOAD_CHUNK(c + NSTAGE, c % NSTAGE);
    }
#undef LOAD_CHUNK

    // epilogue
#pragma unroll
    for (int mb=0;mb<2;mb++){
        int r0 = m0 + wm*32 + mb*16 + (lane>>2);
#pragma unroll
        for (int n8=0;n8<4;n8++){
            int cc = n0 + wn*32 + n8*8 + (lane&3)*2;
            float vx0 = acc[mb][n8][0]*alpha, vy0 = acc[mb][n8][1]*alpha;
            float vx1 = acc[mb][n8][2]*alpha, vy1 = acc[mb][n8][3]*alpha;
            if (SPLITOUT){
                __nv_bfloat162 h0, l0, h1, l1;
                h0.x = __float2bfloat16(vx0); h0.y = __float2bfloat16(vy0);
                l0.x = __float2bfloat16(vx0 - __bfloat162float(h0.x));
                l0.y = __float2bfloat16(vy0 - __bfloat162float(h0.y));
                h1.x = __float2bfloat16(vx1); h1.y = __float2bfloat16(vy1);
                l1.x = __float2bfloat16(vx1 - __bfloat162float(h1.x));
                l1.y = __float2bfloat16(vy1 - __bfloat162float(h1.y));
                *(__nv_bfloat162*)&CH[(long long)r0*ldc + cc] = h0;
                *(__nv_bfloat162*)&CL[(long long)r0*ldc + cc] = l0;
                *(__nv_bfloat162*)&CH[(long long)(r0+8)*ldc + cc] = h1;
                *(__nv_bfloat162*)&CL[(long long)(r0+8)*ldc + cc] = l1;
            } else {
                float2 v0; v0.x = vx0; v0.y = vy0;
                float2 v1; v1.x = vx1; v1.y = vy1;
                *(float2*)&C[(long long)r0*ldc + cc] = v0;
                *(float2*)&C[(long long)(r0+8)*ldc + cc] = v1;
            }
        }
    }
}

// ----------------------------------------------------------------------------
// fp32 -> bf16 hi/lo split
// ----------------------------------------------------------------------------
__global__ void split_plain(const float* __restrict__ X,
                            __nv_bfloat16* __restrict__ H,
                            __nv_bfloat16* __restrict__ L, int n)
{
    int i = (blockIdx.x*blockDim.x + threadIdx.x)*4;
    if (i < n){
        float4 v = *(const float4*)&X[i];
        __nv_bfloat16 h0=__float2bfloat16(v.x), h1=__float2bfloat16(v.y);
        __nv_bfloat16 h2=__float2bfloat16(v.z), h3=__float2bfloat16(v.w);
        __nv_bfloat162 H01; H01.x=h0; H01.y=h1;
        __nv_bfloat162 H23; H23.x=h2; H23.y=h3;
        *(__nv_bfloat162*)&H[i]   = H01;
        *(__nv_bfloat162*)&H[i+2] = H23;
        __nv_bfloat162 L01, L23;
        L01.x = __float2bfloat16(v.x - __bfloat162float(h0));
        L01.y = __float2bfloat16(v.y - __bfloat162float(h1));
        L23.x = __float2bfloat16(v.z - __bfloat162float(h2));
        L23.y = __float2bfloat16(v.w - __bfloat162float(h3));
        *(__nv_bfloat162*)&L[i]   = L01;
        *(__nv_bfloat162*)&L[i+2] = L23;
    }
}

// ----------------------------------------------------------------------------
// RoPE cos/sin tables
// ----------------------------------------------------------------------------
__global__ void rope_tables()
{
    int idx = blockIdx.x*blockDim.x + threadIdx.x;   // 0 .. Sc*64-1
    int s = idx >> 6, i = idx & 63;
    double inv = pow(10000.0, -(double)i/64.0);
    double a = (double)s * inv;
    g_tcos[idx] = (float)cos(a);
    g_tsin[idx] = (float)sin(a);
}

// ----------------------------------------------------------------------------
// RoPE + [B,S,H*D]->[Z,S,D] layout + bf16 hi/lo split (reads g_lin Q/K/V)
// ----------------------------------------------------------------------------
__global__ void rope_split()
{
    long long idx = (long long)blockIdx.x * blockDim.x + threadIdx.x;
    if (idx >= (long long)NELT) return;

    int d = (int)(idx % HDc);
    int h = (int)((idx / HDc) % NHc);
    int s = (int)((idx / HIDc) % Sc);
    int b = (int)(idx / ((long long)Sc * HIDc));
    int z = b*NHc + h;

    long long lin = (long long)(b * Sc + s) * HIDc + h * HDc + d;
    long long out = (long long)(z * Sc + s) * HDc + d;

    const float* Qlin = g_lin;
    const float* Klin = g_lin + NELT;
    const float* Vlin = g_lin + 2*(long long)NELT;

    float q = Qlin[lin];
    float k = Klin[lin];
    float qr, kr;
    if (d < 64) { qr = -Qlin[lin + 64]; kr = -Klin[lin + 64]; }
    else        { qr =  Qlin[lin - 64]; kr =  Klin[lin - 64]; }

    int ti = (s<<6) + (d & 63);
    float c = g_tcos[ti], sn = g_tsin[ti];

    float qv = q * c + qr * sn;
    float kv = k * c + kr * sn;

    __nv_bfloat16 qh = __float2bfloat16(qv);
    g_QH[out] = qh; g_QL[out] = __float2bfloat16(qv - __bfloat162float(qh));
    __nv_bfloat16 kh = __float2bfloat16(kv);
    g_KH[out] = kh; g_KL[out] = __float2bfloat16(kv - __bfloat162float(kh));

    float vv = Vlin[lin];
    __nv_bfloat16 vh = __float2bfloat16(vv);
    g_VH[out] = vh; g_VL[out] = __float2bfloat16(vv - __bfloat162float(vh));
}

// ----------------------------------------------------------------------------
// Causal row softmax
// ----------------------------------------------------------------------------
__global__ void __launch_bounds__(256) softmax_causal(float* __restrict__ P)
{
    __shared__ float smA[9];
    __shared__ float smB[9];
    long long row = blockIdx.x;
    int r = (int)(row & (Sc-1));
    float* p = P + row * Sc;
    const int tid = threadIdx.x;
    const int lane = tid & 31, wid = tid >> 5;

    float v[4];
    float mx = -FLT_MAX;
#pragma unroll
    for (int i = 0; i < 4; i++) {
        int jj = tid + i*256;
        v[i] = (jj <= r) ? p[jj] : -FLT_MAX;
        mx = fmaxf(mx, v[i]);
    }
#pragma unroll
    for (int o = 16; o; o >>= 1) mx = fmaxf(mx, __shfl_xor_sync(0xffffffffu, mx, o));
    if (lane == 0) smA[wid] = mx;
    __syncthreads();
    if (tid < 8) {
        float x = smA[tid];
#pragma unroll
        for (int o = 4; o; o >>= 1) x = fmaxf(x, __shfl_xor_sync(0xffu, x, o));
        if (tid == 0) smA[8] = x;
    }
    __syncthreads();
    mx = smA[8];

    float sum = 0.f;
#pragma unroll
    for (int i = 0; i < 4; i++) { v[i] = expf(v[i] - mx); sum += v[i]; }
#pragma unroll
    for (int o = 16; o; o >>= 1) sum += __shfl_xor_sync(0xffffffffu, sum, o);
    if (lane == 0) smB[wid] = sum;
    __syncthreads();
    if (tid < 8) {
        float x = smB[tid];
#pragma unroll
        for (int o = 4; o; o >>= 1) x += __shfl_xor_sync(0xffu, x, o);
        if (tid == 0) smB[8] = x;
    }
    __syncthreads();
    sum = smB[8];

    float inv = 1.f / sum;
#pragma unroll
    for (int i = 0; i < 4; i++) p[tid + i * 256] = v[i] * inv;
}

// ----------------------------------------------------------------------------
// Sequential heavy-hitter eviction scan (2 barriers/step + prefetch)
// ----------------------------------------------------------------------------
__global__ void __launch_bounds__(1024) scan_kernel(const float* __restrict__ P,
                                                    int* __restrict__ evict)
{
    const int z = blockIdx.x;
    const float* Pz = P + (long long)z * Sc * Sc;
    const int j = threadIdx.x;
    const int lane = j & 31, wid = j >> 5;

    __shared__ float wcoef[CBc];
    __shared__ float sred[32];
    __shared__ unsigned long long mred[32];

    if (j < CBc) wcoef[j] = powf(FFc, (float)(CBc - 1 - j));
    __syncthreads();

    float sel = 0.f;
    for (int i = 0; i < CBc; i++)
        sel += wcoef[i] * Pz[(long long)i * Sc + j];

    const float INFV = __int_as_float(0x7f800000);
    int my_e = 0x7fffffff;

    float sc = __ldg(&Pz[(long long)CBc * Sc + j]);

    for (int t = CBc; t <= Sc - 2; t++) {
        float nxt = 0.f;
        if (t < Sc - 2) nxt = __ldg(&Pz[(long long)(t+1) * Sc + j]);

        bool alive = (sel < INFV);
        float cur = alive ? sc : 0.f;

        float x = cur;
#pragma unroll
        for (int o = 16; o; o >>= 1) x += __shfl_xor_sync(0xffffffffu, x, o);
        if (lane == 0) sred[wid] = x;
        __syncthreads();
        float y = sred[lane];
#pragma unroll
        for (int o = 16; o; o >>= 1) y += __shfl_xor_sync(0xffffffffu, y, o);
        float total = y;

        sel = alive ? (FFc * sel + cur / total) : INFV;

        unsigned long long key = ~0ull;
        if (j >= SBc && j <= t - RBc)
            key = (((unsigned long long)__float_as_uint(sel)) << 32) | (unsigned)j;
#pragma unroll
        for (int o = 16; o; o >>= 1) {
            unsigned long long other = __shfl_xor_sync(0xffffffffu, key, o);
            key = (other < key) ? other : key;
        }
        if (lane == 0) mred[wid] = key;
        __syncthreads();
        unsigned long long y2 = mred[lane];
#pragma unroll
        for (int o = 16; o; o >>= 1) {
            unsigned long long other = __shfl_xor_sync(0xffffffffu, y2, o);
            y2 = (other < y2) ? other : y2;
        }
        int mi = (int)(y2 & 0xffffffffu);
        if (j == mi) { sel = INFV; my_e = t; }

        sc = nxt;
    }

    evict[z * Sc + j] = my_e;
}

// ----------------------------------------------------------------------------
// Keep-mask + renormalize; emit bf16 hi/lo splits
// ----------------------------------------------------------------------------
__global__ void __launch_bounds__(256) maskrenorm_split(const float* __restrict__ P,
                                                        const int* __restrict__ evict,
                                                        __nv_bfloat16* __restrict__ PH,
                                                        __nv_bfloat16* __restrict__ PL)
{
    __shared__ float smB[9];
    long long row = blockIdx.x;
    int z = (int)(row >> 10);
    int r = (int)(row & 1023);
    const float* p = P + row * Sc;
    const int* e = evict + z * Sc;
    const int tid = threadIdx.x;
    const int lane = tid & 31, wid = tid >> 5;

    float v[4];
    float sum = 0.f;
#pragma unroll
    for (int i = 0; i < 4; i++) {
        int jj = tid + i * 256;
        bool keep = (r <= CBc) || (e[jj] >= r);
        v[i] = keep ? p[jj] : 0.f;
        sum += v[i];
    }
#pragma unroll
    for (int o = 16; o; o >>= 1) sum += __shfl_xor_sync(0xffffffffu, sum, o);
    if (lane == 0) smB[wid] = sum;
    __syncthreads();
    if (tid < 8) {
        float x = smB[tid];
#pragma unroll
        for (int o = 4; o; o >>= 1) x += __shfl_xor_sync(0xffu, x, o);
        if (tid == 0) smB[8] = x;
    }
    __syncthreads();
    sum = smB[8];

    float inv = 1.f / sum;
    long long base = row * Sc;
#pragma unroll
    for (int i = 0; i < 4; i++) {
        int jj = tid + i * 256;
        float val = v[i] * inv;
        __nv_bfloat16 h = __float2bfloat16(val);
        PH[base + jj] = h;
        PL[base + jj] = __float2bfloat16(val - __bfloat162float(h));
    }
}

// ----------------------------------------------------------------------------
// Launch
// ----------------------------------------------------------------------------
extern "C" void kernel_launch(void* const* d_in, const int* in_sizes, int n_in,
                              void* d_out, int out_size)
{
    (void)in_sizes; (void)n_in; (void)out_size;
    const float* hs = (const float*)d_in[0];
    const float* wq = (const float*)d_in[1];
    const float* wk = (const float*)d_in[2];
    const float* wv = (const float*)d_in[3];
    const float* wo = (const float*)d_in[4];
    float* out = (float*)d_out;

    float *lin, *P;
    __nv_bfloat16 *hsH, *hsL, *wH, *wL;
    __nv_bfloat16 *QH, *QL, *KH, *KL, *VH, *VL, *PH, *PL, *cH, *cL;
    int* ev;
    cudaGetSymbolAddress((void**)&lin, g_lin);
    cudaGetSymbolAddress((void**)&hsH, g_hsH);  cudaGetSymbolAddress((void**)&hsL, g_hsL);
    cudaGetSymbolAddress((void**)&wH, g_wH);    cudaGetSymbolAddress((void**)&wL, g_wL);
    cudaGetSymbolAddress((void**)&QH, g_QH);    cudaGetSymbolAddress((void**)&QL, g_QL);
    cudaGetSymbolAddress((void**)&KH, g_KH);    cudaGetSymbolAddress((void**)&KL, g_KL);
    cudaGetSymbolAddress((void**)&VH, g_VH);    cudaGetSymbolAddress((void**)&VL, g_VL);
    cudaGetSymbolAddress((void**)&P, g_P);
    cudaGetSymbolAddress((void**)&PH, g_PH);    cudaGetSymbolAddress((void**)&PL, g_PL);
    cudaGetSymbolAddress((void**)&cH, g_cH);    cudaGetSymbolAddress((void**)&cL, g_cL);
    cudaGetSymbolAddress((void**)&ev, g_evict);

    cudaFuncSetAttribute(gemm_mma<true,false,false>,  cudaFuncAttributeMaxDynamicSharedMemorySize, GSMEM_TOTAL);
    cudaFuncSetAttribute(gemm_mma<false,true,false>,  cudaFuncAttributeMaxDynamicSharedMemorySize, GSMEM_TOTAL);
    cudaFuncSetAttribute(gemm_mma<true,false,true>,   cudaFuncAttributeMaxDynamicSharedMemorySize, GSMEM_TOTAL);

    const float qk_scale = 0.08838834764831845f;  // 1/sqrt(128)
    const int splitBlocks = NELT/4/256;

    // 0) RoPE tables
    rope_tables<<<(Sc*64)/256, 256>>>();

    // 1) bf16 hi/lo splits (weights into one contiguous buffer: q,k,v,o)
    split_plain<<<splitBlocks, 256>>>(hs, hsH, hsL, NELT);
    split_plain<<<splitBlocks, 256>>>(wq, wH + 0*(size_t)HIDc*HIDc, wL + 0*(size_t)HIDc*HIDc, NELT);
    split_plain<<<splitBlocks, 256>>>(wk, wH + 1*(size_t)HIDc*HIDc, wL + 1*(size_t)HIDc*HIDc, NELT);
    split_plain<<<splitBlocks, 256>>>(wv, wH + 2*(size_t)HIDc*HIDc, wL + 2*(size_t)HIDc*HIDc, NELT);
    split_plain<<<splitBlocks, 256>>>(wo, wH + 3*(size_t)HIDc*HIDc, wL + 3*(size_t)HIDc*HIDc, NELT);

    // 2) Fused QKV projections: grid.z selects weight + output slice
    gemm_mma<true,false,false><<<dim3(16,16,3), 512, GSMEM_TOTAL>>>(hsH, hsL, wH, wL, lin,
        nullptr, nullptr, HIDc, HIDc, HIDc,
        0, (long long)HIDc*HIDc, (long long)NELT, 0, 1, 1.f);

    // 3) RoPE + layout + split
    rope_split<<<NELT/256, 256>>>();

    // 4) QK^T causal, scaled
    gemm_mma<false,true,false><<<dim3(8,8,ZB), 512, GSMEM_TOTAL>>>(QH, QL, KH, KL, P,
        nullptr, nullptr, HDc, HDc, Sc,
        (long long)Sc*HDc, (long long)Sc*HDc,
        (long long)Sc*Sc, 0, 1, qk_scale);

    // 5) softmax
    softmax_causal<<<ZB*Sc, 256>>>(P);

    // 6) eviction scan
    scan_kernel<<<ZB, 1024>>>(P, ev);

    // 7) mask + renormalize -> bf16 splits
    maskrenorm_split<<<ZB*Sc, 256>>>(P, ev, PH, PL);

    // 8) PV -> ctx (bf16 hi/lo direct)
    gemm_mma<true,false,true><<<dim3(1,8,ZB), 512, GSMEM_TOTAL>>>(PH, PL, VH, VL,
        nullptr, cH, cL, Sc, HDc, HIDc,
        (long long)Sc*Sc, (long long)Sc*HDc,
        (long long)Sc*HIDc, (long long)HDc, NHc, 1.f);

    // 9) output projection
    gemm_mma<true,false,false><<<dim3(16,16,1), 512, GSMEM_TOTAL>>>(cH, cL,
        wH + 3*(size_t)HIDc*HIDc, wL + 3*(size_t)HIDc*HIDc, out,
        nullptr, nullptr, HIDc, HIDc, HIDc, 0, 0, 0, 0, 1, 1.f);
}

// round 7
// speedup vs baseline: 1.0699x; 1.0568x over previous
#include <cuda_runtime.h>
#include <cuda_bf16.h>
#include <math.h>
#include <float.h>
#include <stdint.h>

// Problem constants
#define Bc    2
#define Sc    1024
#define HIDc  2048
#define NHc   16
#define HDc   128
#define SBc   20
#define RBc   82
#define CBc   163
#define FFc   0.9f
#define BSc   (Bc*Sc)          // 2048
#define ZB    (Bc*NHc)         // 32
#define NELT  (BSc*HIDc)       // 4M

// ----------------------------------------------------------------------------
// Scratch
// ----------------------------------------------------------------------------
__device__ __align__(1024) float g_lin[3*NELT];                  // Q,K,V linear
__device__ __align__(1024) __nv_bfloat16 g_hsH[NELT];
__device__ __align__(1024) __nv_bfloat16 g_hsL[NELT];
__device__ __align__(1024) __nv_bfloat16 g_wH[4*HIDc*HIDc];      // wq,wk,wv,wo
__device__ __align__(1024) __nv_bfloat16 g_wL[4*HIDc*HIDc];
__device__ __align__(1024) __nv_bfloat16 g_QH[ZB*Sc*HDc];
__device__ __align__(1024) __nv_bfloat16 g_QL[ZB*Sc*HDc];
__device__ __align__(1024) __nv_bfloat16 g_KH[ZB*Sc*HDc];
__device__ __align__(1024) __nv_bfloat16 g_KL[ZB*Sc*HDc];
__device__ __align__(1024) __nv_bfloat16 g_VH[ZB*Sc*HDc];
__device__ __align__(1024) __nv_bfloat16 g_VL[ZB*Sc*HDc];
__device__ __align__(1024) float g_P[(size_t)ZB*Sc*Sc];
__device__ __align__(1024) __nv_bfloat16 g_PH[(size_t)ZB*Sc*Sc];
__device__ __align__(1024) __nv_bfloat16 g_PL[(size_t)ZB*Sc*Sc];
__device__ __align__(1024) __nv_bfloat16 g_cH[NELT];
__device__ __align__(1024) __nv_bfloat16 g_cL[NELT];
__device__ int g_evict[ZB*Sc];
__device__ float g_tcos[Sc*64];
__device__ float g_tsin[Sc*64];

// ----------------------------------------------------------------------------
// PTX helpers
// ----------------------------------------------------------------------------
__device__ __forceinline__ uint32_t smem_u32(const void* p){
    uint32_t a;
    asm("{ .reg .u64 t; cvta.to.shared.u64 t, %1; cvt.u32.u64 %0, t; }":"=r"(a):"l"(p));
    return a;
}
__device__ __forceinline__ void cp16(uint32_t d, const void* s){
    asm volatile("cp.async.cg.shared.global [%0], [%1], 16;"::"r"(d),"l"(s));
}
#define CP_COMMIT() asm volatile("cp.async.commit_group;":::"memory")
#define CP_WAIT(n)  asm volatile("cp.async.wait_group %0;"::"n"(n):"memory")

__device__ __forceinline__ void ldsm4(uint32_t r[4], uint32_t a){
    asm volatile("ldmatrix.sync.aligned.m8n8.x4.shared.b16 {%0,%1,%2,%3}, [%4];"
        : "=r"(r[0]),"=r"(r[1]),"=r"(r[2]),"=r"(r[3]) : "r"(a));
}
__device__ __forceinline__ void ldsm4t(uint32_t r[4], uint32_t a){
    asm volatile("ldmatrix.sync.aligned.m8n8.x4.trans.shared.b16 {%0,%1,%2,%3}, [%4];"
        : "=r"(r[0]),"=r"(r[1]),"=r"(r[2]),"=r"(r[3]) : "r"(a));
}
__device__ __forceinline__ void mma16816(float d[4], const uint32_t a[4], const uint32_t b[2]){
    asm volatile("mma.sync.aligned.m16n8k16.row.col.f32.bf16.bf16.f32 "
        "{%0,%1,%2,%3},{%4,%5,%6,%7},{%8,%9},{%0,%1,%2,%3};"
        : "+f"(d[0]),"+f"(d[1]),"+f"(d[2]),"+f"(d[3])
        : "r"(a[0]),"r"(a[1]),"r"(a[2]),"r"(a[3]),"r"(b[0]),"r"(b[1]));
}

#define GSMEM_TOTAL 196608   // 192 KB

// Copy [NROWS x 64 bf16] tile, rowbytes=128, XOR-(r&7) chunk swizzle. 256 thr.
template<int NROWS>
__device__ __forceinline__ void copy_rk(uint32_t dst, const __nv_bfloat16* src,
                                        int ld, int tid){
#pragma unroll
    for (int i=0;i<NROWS*8/256;i++){
        int idx = tid + i*256;
        int r = idx>>3, c = idx&7;
        uint32_t sw = (uint32_t)(r*128) + (uint32_t)(((c ^ (r&7))<<4));
        cp16(dst + sw, (const char*)src + ((long long)r*ld + c*8)*2);
    }
}
// Copy [64 rows(k) x NCOLS bf16(n)] tile, rowbytes=NCOLS*2, XOR swizzle.
template<int NCOLS>
__device__ __forceinline__ void copy_kn(uint32_t dst, const __nv_bfloat16* src,
                                        int ld, int tid){
    const int CPR = NCOLS/8;
#pragma unroll
    for (int i=0;i<64*CPR/256;i++){
        int idx = tid + i*256;
        int r = idx/CPR, c = idx%CPR;
        uint32_t sw = (uint32_t)(r*(NCOLS*2)) + (uint32_t)(((c ^ (r&7))<<4));
        cp16(dst + sw, (const char*)src + ((long long)r*ld + c*8)*2);
    }
}

// ----------------------------------------------------------------------------
// HMMA GEMM: C[M,N] = alpha*(Ah+Al)[M,K] @ (Bh+Bl)^T, fp32 acc, 3-term split.
// NT: CTA tile N width (128 or 256). CTA tile M = 128. 8 warps (2x4),
// warp tile 64 x NT/4. K-chunk 64. NT=128: 3-stage; NT=256: 2-stage (192KB).
// BKN: B stored [K,N] (trans ldmatrix) vs [N,K]. CAUSAL: skip blocks above
// diagonal. SPLITOUT: emit bf16 hi/lo. KTRUNC: K-loop stops at m0+128 (PV).
// ----------------------------------------------------------------------------
template<int NT, bool BKN, bool CAUSAL, bool SPLITOUT, bool KTRUNC>
__global__ void __launch_bounds__(256) gemm_mma(
    const __nv_bfloat16* __restrict__ Ah, const __nv_bfloat16* __restrict__ Al,
    const __nv_bfloat16* __restrict__ Bh, const __nv_bfloat16* __restrict__ Bl,
    float* __restrict__ C,
    __nv_bfloat16* __restrict__ CH, __nv_bfloat16* __restrict__ CL,
    int K, int ldb, int ldc,
    long long sA, long long sB, long long sCo, long long sCi, int ndiv, float alpha)
{
    const int m0 = blockIdx.y*128, n0 = blockIdx.x*NT, z = blockIdx.z;
    if (CAUSAL && n0 > m0 + 127) return;
    const int NN8 = NT/32;            // n8 groups per warp (4 or 8)
    const int TILEA = 16384;          // A tile bytes (128x64)
    const int TILEBB = NT*128;        // B tile bytes
    const int STG = 2*TILEA + 2*TILEBB;
    const int NS = (NT==256) ? 2 : 3;

    extern __shared__ __align__(1024) char smem[];
    const uint32_t sb = smem_u32(smem);
    Ah += (long long)z*sA; Al += (long long)z*sA;
    Bh += (long long)z*sB; Bl += (long long)z*sB;
    long long coff = (long long)(z/ndiv)*sCo + (long long)(z%ndiv)*sCi;
    if (SPLITOUT){ CH += coff; CL += coff; } else { C += coff; }

    const int tid = threadIdx.x, lane = tid&31, wid = tid>>5;
    const int wm = wid>>2, wn = wid&3;   // 2x4 warp grid, 64 x NT/4 warp tiles

    float acc[4][NN8][4];
#pragma unroll
    for (int a=0;a<4;a++)
#pragma unroll
        for (int b=0;b<NN8;b++)
#pragma unroll
            for (int c=0;c<4;c++) acc[a][b][c] = 0.f;

    const int nch = KTRUNC ? ((m0+128)>>6) : (K>>6);

#define LOAD_CHUNK(cc, ss) do{ \
    uint32_t bbase = sb + (uint32_t)(ss)*STG; \
    copy_rk<128>(bbase,         Ah + (long long)m0*K + (cc)*64, K, tid); \
    copy_rk<128>(bbase + TILEA, Al + (long long)m0*K + (cc)*64, K, tid); \
    if (BKN){ \
        copy_kn<NT>(bbase + 2*TILEA,          Bh + (long long)(cc)*64*ldb + n0, ldb, tid); \
        copy_kn<NT>(bbase + 2*TILEA + TILEBB, Bl + (long long)(cc)*64*ldb + n0, ldb, tid); \
    } else { \
        copy_rk<NT>(bbase + 2*TILEA,          Bh + (long long)n0*K + (cc)*64, K, tid); \
        copy_rk<NT>(bbase + 2*TILEA + TILEBB, Bl + (long long)n0*K + (cc)*64, K, tid); \
    } \
    CP_COMMIT(); }while(0)

    LOAD_CHUNK(0, 0);
    if (NS > 1 && nch > 1) LOAD_CHUNK(1, 1);
    if (NS > 2 && nch > 2) LOAD_CHUNK(2, 2);

    const uint32_t axor = (uint32_t)(lane&7);

    for (int c=0; c<nch; c++){
        int pend = nch-1-c; if (pend > NS-1) pend = NS-1;
        if (pend >= 2) CP_WAIT(2);
        else if (pend == 1) CP_WAIT(1);
        else CP_WAIT(0);
        __syncthreads();
        uint32_t base = sb + (uint32_t)(c % NS)*STG;
#pragma unroll
        for (int ks=0; ks<4; ks++){
            uint32_t bh[NN8][2], bl[NN8][2];
#pragma unroll
            for (int nb=0;nb<NN8/2;nb++){
                uint32_t t[4];
                if (BKN){
                    uint32_t row = (uint32_t)(ks*16 + (lane&7) + (((lane>>3)&1)<<3));
                    uint32_t ch  = ((uint32_t)(wn*NN8 + nb*2 + (lane>>4)) ^ axor);
                    uint32_t ad  = base + 2*TILEA + row*(NT*2) + (ch<<4);
                    ldsm4t(t, ad);
                    bh[2*nb][0]=t[0]; bh[2*nb][1]=t[1]; bh[2*nb+1][0]=t[2]; bh[2*nb+1][1]=t[3];
                    ldsm4t(t, ad + TILEBB);
                    bl[2*nb][0]=t[0]; bl[2*nb][1]=t[1]; bl[2*nb+1][0]=t[2]; bl[2*nb+1][1]=t[3];
                } else {
                    uint32_t row = (uint32_t)(wn*(NT/4) + nb*16 + (lane&7) + ((lane>>4)<<3));
                    uint32_t ch  = ((uint32_t)(ks*2 + ((lane>>3)&1)) ^ axor);
                    uint32_t ad  = base + 2*TILEA + row*128 + (ch<<4);
                    ldsm4(t, ad);
                    bh[2*nb][0]=t[0]; bh[2*nb][1]=t[1]; bh[2*nb+1][0]=t[2]; bh[2*nb+1][1]=t[3];
                    ldsm4(t, ad + TILEBB);
                    bl[2*nb][0]=t[0]; bl[2*nb][1]=t[1]; bl[2*nb+1][0]=t[2]; bl[2*nb+1][1]=t[3];
                }
            }
#pragma unroll
            for (int mb=0;mb<4;mb++){
                uint32_t ah[4], al[4];
                uint32_t row = (uint32_t)(wm*64 + mb*16 + (lane&15));
                uint32_t col = (((uint32_t)(ks*2 + (lane>>4)) ^ (row&7u))<<4);
                uint32_t ad = base + row*128 + col;
                ldsm4(ah, ad);
                ldsm4(al, ad + TILEA);
#pragma unroll
                for (int n8=0;n8<NN8;n8++){
                    mma16816(acc[mb][n8], ah, bh[n8]);
                    mma16816(acc[mb][n8], ah, bl[n8]);
                    mma16816(acc[mb][n8], al, bh[n8]);
                }
            }
        }
        __syncthreads();
        if (c + NS < nch) LOAD_CHUNK(c + NS, c % NS);
    }
#undef LOAD_CHUNK

    // epilogue
#pragma unroll
    for (int mb=0;mb<4;mb++){
        int r0 = m0 + wm*64 + mb*16 + (lane>>2);
#pragma unroll
        for (int n8=0;n8<NN8;n8++){
            int cc = n0 + wn*(NT/4) + n8*8 + (lane&3)*2;
            float vx0 = acc[mb][n8][0]*alpha, vy0 = acc[mb][n8][1]*alpha;
            float vx1 = acc[mb][n8][2]*alpha, vy1 = acc[mb][n8][3]*alpha;
            if (SPLITOUT){
                __nv_bfloat162 h0, l0, h1, l1;
                h0.x = __float2bfloat16(vx0); h0.y = __float2bfloat16(vy0);
                l0.x = __float2bfloat16(vx0 - __bfloat162float(h0.x));
                l0.y = __float2bfloat16(vy0 - __bfloat162float(h0.y));
                h1.x = __float2bfloat16(vx1); h1.y = __float2bfloat16(vy1);
                l1.x = __float2bfloat16(vx1 - __bfloat162float(h1.x));
                l1.y = __float2bfloat16(vy1 - __bfloat162float(h1.y));
                *(__nv_bfloat162*)&CH[(long long)r0*ldc + cc] = h0;
                *(__nv_bfloat162*)&CL[(long long)r0*ldc + cc] = l0;
                *(__nv_bfloat162*)&CH[(long long)(r0+8)*ldc + cc] = h1;
                *(__nv_bfloat162*)&CL[(long long)(r0+8)*ldc + cc] = l1;
            } else {
                float2 v0; v0.x = vx0; v0.y = vy0;
                float2 v1; v1.x = vx1; v1.y = vy1;
                *(float2*)&C[(long long)r0*ldc + cc] = v0;
                *(float2*)&C[(long long)(r0+8)*ldc + cc] = v1;
            }
        }
    }
}

// ----------------------------------------------------------------------------
// fp32 -> bf16 hi/lo split
// ----------------------------------------------------------------------------
__global__ void split_plain(const float* __restrict__ X,
                            __nv_bfloat16* __restrict__ H,
                            __nv_bfloat16* __restrict__ L, int n)
{
    int i = (blockIdx.x*blockDim.x + threadIdx.x)*4;
    if (i < n){
        float4 v = *(const float4*)&X[i];
        __nv_bfloat16 h0=__float2bfloat16(v.x), h1=__float2bfloat16(v.y);
        __nv_bfloat16 h2=__float2bfloat16(v.z), h3=__float2bfloat16(v.w);
        __nv_bfloat162 H01; H01.x=h0; H01.y=h1;
        __nv_bfloat162 H23; H23.x=h2; H23.y=h3;
        *(__nv_bfloat162*)&H[i]   = H01;
        *(__nv_bfloat162*)&H[i+2] = H23;
        __nv_bfloat162 L01, L23;
        L01.x = __float2bfloat16(v.x - __bfloat162float(h0));
        L01.y = __float2bfloat16(v.y - __bfloat162float(h1));
        L23.x = __float2bfloat16(v.z - __bfloat162float(h2));
        L23.y = __float2bfloat16(v.w - __bfloat162float(h3));
        *(__nv_bfloat162*)&L[i]   = L01;
        *(__nv_bfloat162*)&L[i+2] = L23;
    }
}

// ----------------------------------------------------------------------------
// RoPE cos/sin tables
// ----------------------------------------------------------------------------
__global__ void rope_tables()
{
    int idx = blockIdx.x*blockDim.x + threadIdx.x;   // 0 .. Sc*64-1
    int s = idx >> 6, i = idx & 63;
    double inv = pow(10000.0, -(double)i/64.0);
    double a = (double)s * inv;
    g_tcos[idx] = (float)cos(a);
    g_tsin[idx] = (float)sin(a);
}

// ----------------------------------------------------------------------------
// RoPE + [B,S,H*D]->[Z,S,D] layout + bf16 hi/lo split
// ----------------------------------------------------------------------------
__global__ void rope_split()
{
    long long idx = (long long)blockIdx.x * blockDim.x + threadIdx.x;
    if (idx >= (long long)NELT) return;

    int d = (int)(idx % HDc);
    int h = (int)((idx / HDc) % NHc);
    int s = (int)((idx / HIDc) % Sc);
    int b = (int)(idx / ((long long)Sc * HIDc));
    int z = b*NHc + h;

    long long lin = (long long)(b * Sc + s) * HIDc + h * HDc + d;
    long long out = (long long)(z * Sc + s) * HDc + d;

    const float* Qlin = g_lin;
    const float* Klin = g_lin + NELT;
    const float* Vlin = g_lin + 2*(long long)NELT;

    float q = Qlin[lin];
    float k = Klin[lin];
    float qr, kr;
    if (d < 64) { qr = -Qlin[lin + 64]; kr = -Klin[lin + 64]; }
    else        { qr =  Qlin[lin - 64]; kr =  Klin[lin - 64]; }

    int ti = (s<<6) + (d & 63);
    float c = g_tcos[ti], sn = g_tsin[ti];

    float qv = q * c + qr * sn;
    float kv = k * c + kr * sn;

    __nv_bfloat16 qh = __float2bfloat16(qv);
    g_QH[out] = qh; g_QL[out] = __float2bfloat16(qv - __bfloat162float(qh));
    __nv_bfloat16 kh = __float2bfloat16(kv);
    g_KH[out] = kh; g_KL[out] = __float2bfloat16(kv - __bfloat162float(kh));

    float vv = Vlin[lin];
    __nv_bfloat16 vh = __float2bfloat16(vv);
    g_VH[out] = vh; g_VL[out] = __float2bfloat16(vv - __bfloat162float(vh));
}

// ----------------------------------------------------------------------------
// Causal row softmax
// ----------------------------------------------------------------------------
__global__ void __launch_bounds__(256) softmax_causal(float* __restrict__ P)
{
    __shared__ float smA[9];
    __shared__ float smB[9];
    long long row = blockIdx.x;
    int r = (int)(row & (Sc-1));
    float* p = P + row * Sc;
    const int tid = threadIdx.x;
    const int lane = tid & 31, wid = tid >> 5;

    float v[4];
    float mx = -FLT_MAX;
#pragma unroll
    for (int i = 0; i < 4; i++) {
        int jj = tid + i*256;
        v[i] = (jj <= r) ? p[jj] : -FLT_MAX;
        mx = fmaxf(mx, v[i]);
    }
#pragma unroll
    for (int o = 16; o; o >>= 1) mx = fmaxf(mx, __shfl_xor_sync(0xffffffffu, mx, o));
    if (lane == 0) smA[wid] = mx;
    __syncthreads();
    if (tid < 8) {
        float x = smA[tid];
#pragma unroll
        for (int o = 4; o; o >>= 1) x = fmaxf(x, __shfl_xor_sync(0xffu, x, o));
        if (tid == 0) smA[8] = x;
    }
    __syncthreads();
    mx = smA[8];

    float sum = 0.f;
#pragma unroll
    for (int i = 0; i < 4; i++) { v[i] = expf(v[i] - mx); sum += v[i]; }
#pragma unroll
    for (int o = 16; o; o >>= 1) sum += __shfl_xor_sync(0xffffffffu, sum, o);
    if (lane == 0) smB[wid] = sum;
    __syncthreads();
    if (tid < 8) {
        float x = smB[tid];
#pragma unroll
        for (int o = 4; o; o >>= 1) x += __shfl_xor_sync(0xffu, x, o);
        if (tid == 0) smB[8] = x;
    }
    __syncthreads();
    sum = smB[8];

    float inv = 1.f / sum;
#pragma unroll
    for (int i = 0; i < 4; i++) p[tid + i * 256] = v[i] * inv;
}

// ----------------------------------------------------------------------------
// Sequential heavy-hitter eviction scan (2 barriers/step + prefetch)
// ----------------------------------------------------------------------------
__global__ void __launch_bounds__(1024) scan_kernel(const float* __restrict__ P,
                                                    int* __restrict__ evict)
{
    const int z = blockIdx.x;
    const float* Pz = P + (long long)z * Sc * Sc;
    const int j = threadIdx.x;
    const int lane = j & 31, wid = j >> 5;

    __shared__ float wcoef[CBc];
    __shared__ float sred[32];
    __shared__ unsigned long long mred[32];

    if (j < CBc) wcoef[j] = powf(FFc, (float)(CBc - 1 - j));
    __syncthreads();

    float sel = 0.f;
    for (int i = 0; i < CBc; i++)
        sel += wcoef[i] * Pz[(long long)i * Sc + j];

    const float INFV = __int_as_float(0x7f800000);
    int my_e = 0x7fffffff;

    float sc = __ldg(&Pz[(long long)CBc * Sc + j]);

    for (int t = CBc; t <= Sc - 2; t++) {
        float nxt = 0.f;
        if (t < Sc - 2) nxt = __ldg(&Pz[(long long)(t+1) * Sc + j]);

        bool alive = (sel < INFV);
        float cur = alive ? sc : 0.f;

        float x = cur;
#pragma unroll
        for (int o = 16; o; o >>= 1) x += __shfl_xor_sync(0xffffffffu, x, o);
        if (lane == 0) sred[wid] = x;
        __syncthreads();
        float y = sred[lane];
#pragma unroll
        for (int o = 16; o; o >>= 1) y += __shfl_xor_sync(0xffffffffu, y, o);
        float total = y;

        sel = alive ? (FFc * sel + cur / total) : INFV;

        unsigned long long key = ~0ull;
        if (j >= SBc && j <= t - RBc)
            key = (((unsigned long long)__float_as_uint(sel)) << 32) | (unsigned)j;
#pragma unroll
        for (int o = 16; o; o >>= 1) {
            unsigned long long other = __shfl_xor_sync(0xffffffffu, key, o);
            key = (other < key) ? other : key;
        }
        if (lane == 0) mred[wid] = key;
        __syncthreads();
        unsigned long long y2 = mred[lane];
#pragma unroll
        for (int o = 16; o; o >>= 1) {
            unsigned long long other = __shfl_xor_sync(0xffffffffu, y2, o);
            y2 = (other < y2) ? other : y2;
        }
        int mi = (int)(y2 & 0xffffffffu);
        if (j == mi) { sel = INFV; my_e = t; }

        sc = nxt;
    }

    evict[z * Sc + j] = my_e;
}

// ----------------------------------------------------------------------------
// Keep-mask + renormalize; emit bf16 hi/lo splits
// ----------------------------------------------------------------------------
__global__ void __launch_bounds__(256) maskrenorm_split(const float* __restrict__ P,
                                                        const int* __restrict__ evict,
                                                        __nv_bfloat16* __restrict__ PH,
                                                        __nv_bfloat16* __restrict__ PL)
{
    __shared__ float smB[9];
    long long row = blockIdx.x;
    int z = (int)(row >> 10);
    int r = (int)(row & 1023);
    const float* p = P + row * Sc;
    const int* e = evict + z * Sc;
    const int tid = threadIdx.x;
    const int lane = tid & 31, wid = tid >> 5;

    float v[4];
    float sum = 0.f;
#pragma unroll
    for (int i = 0; i < 4; i++) {
        int jj = tid + i * 256;
        bool keep = (r <= CBc) || (e[jj] >= r);
        v[i] = keep ? p[jj] : 0.f;
        sum += v[i];
    }
#pragma unroll
    for (int o = 16; o; o >>= 1) sum += __shfl_xor_sync(0xffffffffu, sum, o);
    if (lane == 0) smB[wid] = sum;
    __syncthreads();
    if (tid < 8) {
        float x = smB[tid];
#pragma unroll
        for (int o = 4; o; o >>= 1) x += __shfl_xor_sync(0xffu, x, o);
        if (tid == 0) smB[8] = x;
    }
    __syncthreads();
    sum = smB[8];

    float inv = 1.f / sum;
    long long base = row * Sc;
#pragma unroll
    for (int i = 0; i < 4; i++) {
        int jj = tid + i * 256;
        float val = v[i] * inv;
        __nv_bfloat16 h = __float2bfloat16(val);
        PH[base + jj] = h;
        PL[base + jj] = __float2bfloat16(val - __bfloat162float(h));
    }
}

// ----------------------------------------------------------------------------
// Launch
// ----------------------------------------------------------------------------
extern "C" void kernel_launch(void* const* d_in, const int* in_sizes, int n_in,
                              void* d_out, int out_size)
{
    (void)in_sizes; (void)n_in; (void)out_size;
    const float* hs = (const float*)d_in[0];
    const float* wq = (const float*)d_in[1];
    const float* wk = (const float*)d_in[2];
    const float* wv = (const float*)d_in[3];
    const float* wo = (const float*)d_in[4];
    float* out = (float*)d_out;

    float *lin, *P;
    __nv_bfloat16 *hsH, *hsL, *wH, *wL;
    __nv_bfloat16 *QH, *QL, *KH, *KL, *VH, *VL, *PH, *PL, *cH, *cL;
    int* ev;
    cudaGetSymbolAddress((void**)&lin, g_lin);
    cudaGetSymbolAddress((void**)&hsH, g_hsH);  cudaGetSymbolAddress((void**)&hsL, g_hsL);
    cudaGetSymbolAddress((void**)&wH, g_wH);    cudaGetSymbolAddress((void**)&wL, g_wL);
    cudaGetSymbolAddress((void**)&QH, g_QH);    cudaGetSymbolAddress((void**)&QL, g_QL);
    cudaGetSymbolAddress((void**)&KH, g_KH);    cudaGetSymbolAddress((void**)&KL, g_KL);
    cudaGetSymbolAddress((void**)&VH, g_VH);    cudaGetSymbolAddress((void**)&VL, g_VL);
    cudaGetSymbolAddress((void**)&P, g_P);
    cudaGetSymbolAddress((void**)&PH, g_PH);    cudaGetSymbolAddress((void**)&PL, g_PL);
    cudaGetSymbolAddress((void**)&cH, g_cH);    cudaGetSymbolAddress((void**)&cL, g_cL);
    cudaGetSymbolAddress((void**)&ev, g_evict);

    cudaFuncSetAttribute((const void*)gemm_mma<256,true,false,false,false>,
                         cudaFuncAttributeMaxDynamicSharedMemorySize, GSMEM_TOTAL);
    cudaFuncSetAttribute((const void*)gemm_mma<256,false,true,false,false>,
                         cudaFuncAttributeMaxDynamicSharedMemorySize, GSMEM_TOTAL);
    cudaFuncSetAttribute((const void*)gemm_mma<128,true,false,true,true>,
                         cudaFuncAttributeMaxDynamicSharedMemorySize, GSMEM_TOTAL);

    const float qk_scale = 0.08838834764831845f;  // 1/sqrt(128)
    const int splitBlocks = NELT/4/256;

    // 0) RoPE tables
    rope_tables<<<(Sc*64)/256, 256>>>();

    // 1) bf16 hi/lo splits (weights into one contiguous buffer: q,k,v,o)
    split_plain<<<splitBlocks, 256>>>(hs, hsH, hsL, NELT);
    split_plain<<<splitBlocks, 256>>>(wq, wH + 0*(size_t)HIDc*HIDc, wL + 0*(size_t)HIDc*HIDc, NELT);
    split_plain<<<splitBlocks, 256>>>(wk, wH + 1*(size_t)HIDc*HIDc, wL + 1*(size_t)HIDc*HIDc, NELT);
    split_plain<<<splitBlocks, 256>>>(wv, wH + 2*(size_t)HIDc*HIDc, wL + 2*(size_t)HIDc*HIDc, NELT);
    split_plain<<<splitBlocks, 256>>>(wo, wH + 3*(size_t)HIDc*HIDc, wL + 3*(size_t)HIDc*HIDc, NELT);

    // 2) Fused QKV projections (NT=256): grid.z selects weight + output slice
    gemm_mma<256,true,false,false,false><<<dim3(8,16,3), 256, GSMEM_TOTAL>>>(
        hsH, hsL, wH, wL, lin, nullptr, nullptr, HIDc, HIDc, HIDc,
        0, (long long)HIDc*HIDc, (long long)NELT, 0, 1, 1.f);

    // 3) RoPE + layout + split
    rope_split<<<NELT/256, 256>>>();

    // 4) QK^T causal, scaled (NT=256)
    gemm_mma<256,false,true,false,false><<<dim3(4,8,ZB), 256, GSMEM_TOTAL>>>(
        QH, QL, KH, KL, P, nullptr, nullptr, HDc, HDc, Sc,
        (long long)Sc*HDc, (long long)Sc*HDc,
        (long long)Sc*Sc, 0, 1, qk_scale);

    // 5) softmax
    softmax_causal<<<ZB*Sc, 256>>>(P);

    // 6) eviction scan
    scan_kernel<<<ZB, 1024>>>(P, ev);

    // 7) mask + renormalize -> bf16 splits
    maskrenorm_split<<<ZB*Sc, 256>>>(P, ev, PH, PL);

    // 8) PV -> ctx (NT=128, K truncated at diagonal, bf16 hi/lo out)
    gemm_mma<128,true,false,true,true><<<dim3(1,8,ZB), 256, GSMEM_TOTAL>>>(
        PH, PL, VH, VL, nullptr, cH, cL, Sc, HDc, HIDc,
        (long long)Sc*Sc, (long long)Sc*HDc,
        (long long)Sc*HIDc, (long long)HDc, NHc, 1.f);

    // 9) output projection (NT=256)
    gemm_mma<256,true,false,false,false><<<dim3(8,16,1), 256, GSMEM_TOTAL>>>(
        cH, cL, wH + 3*(size_t)HIDc*HIDc, wL + 3*(size_t)HIDc*HIDc, out,
        nullptr, nullptr, HIDc, HIDc, HIDc, 0, 0, 0, 0, 1, 1.f);
}

// round 8
// speedup vs baseline: 1.1928x; 1.1149x over previous
#include <cuda_runtime.h>
#include <cuda_bf16.h>
#include <math.h>
#include <float.h>
#include <stdint.h>

// Problem constants
#define Bc    2
#define Sc    1024
#define HIDc  2048
#define NHc   16
#define HDc   128
#define SBc   20
#define RBc   82
#define CBc   163
#define FFc   0.9f
#define BSc   (Bc*Sc)          // 2048
#define ZB    (Bc*NHc)         // 32
#define NELT  (BSc*HIDc)       // 4M

// ----------------------------------------------------------------------------
// Scratch
// ----------------------------------------------------------------------------
__device__ __align__(1024) float g_lin[3*NELT];                  // Q,K,V linear
__device__ __align__(1024) __nv_bfloat16 g_hsH[NELT];
__device__ __align__(1024) __nv_bfloat16 g_hsL[NELT];
__device__ __align__(1024) __nv_bfloat16 g_wH[4*HIDc*HIDc];      // wq,wk,wv,wo
__device__ __align__(1024) __nv_bfloat16 g_wL[4*HIDc*HIDc];
__device__ __align__(1024) __nv_bfloat16 g_QH[ZB*Sc*HDc];
__device__ __align__(1024) __nv_bfloat16 g_QL[ZB*Sc*HDc];
__device__ __align__(1024) __nv_bfloat16 g_KH[ZB*Sc*HDc];
__device__ __align__(1024) __nv_bfloat16 g_KL[ZB*Sc*HDc];
__device__ __align__(1024) __nv_bfloat16 g_VH[ZB*Sc*HDc];
__device__ __align__(1024) __nv_bfloat16 g_VL[ZB*Sc*HDc];
__device__ __align__(1024) float g_P[(size_t)ZB*Sc*Sc];
__device__ __align__(1024) __nv_bfloat16 g_PH[(size_t)ZB*Sc*Sc];
__device__ __align__(1024) __nv_bfloat16 g_PL[(size_t)ZB*Sc*Sc];
__device__ __align__(1024) __nv_bfloat16 g_cH[NELT];
__device__ __align__(1024) __nv_bfloat16 g_cL[NELT];
__device__ int g_evict[ZB*Sc];
__device__ float g_tcos[Sc*64];
__device__ float g_tsin[Sc*64];
__device__ float g_wcoef[CBc];

// ----------------------------------------------------------------------------
// PTX helpers
// ----------------------------------------------------------------------------
__device__ __forceinline__ uint32_t smem_u32(const void* p){
    uint32_t a;
    asm("{ .reg .u64 t; cvta.to.shared.u64 t, %1; cvt.u32.u64 %0, t; }":"=r"(a):"l"(p));
    return a;
}
__device__ __forceinline__ void cp16(uint32_t d, const void* s){
    asm volatile("cp.async.cg.shared.global [%0], [%1], 16;"::"r"(d),"l"(s));
}
#define CP_COMMIT() asm volatile("cp.async.commit_group;":::"memory")
#define CP_WAIT(n)  asm volatile("cp.async.wait_group %0;"::"n"(n):"memory")

__device__ __forceinline__ void ldsm4(uint32_t r[4], uint32_t a){
    asm volatile("ldmatrix.sync.aligned.m8n8.x4.shared.b16 {%0,%1,%2,%3}, [%4];"
        : "=r"(r[0]),"=r"(r[1]),"=r"(r[2]),"=r"(r[3]) : "r"(a));
}
__device__ __forceinline__ void ldsm4t(uint32_t r[4], uint32_t a){
    asm volatile("ldmatrix.sync.aligned.m8n8.x4.trans.shared.b16 {%0,%1,%2,%3}, [%4];"
        : "=r"(r[0]),"=r"(r[1]),"=r"(r[2]),"=r"(r[3]) : "r"(a));
}
__device__ __forceinline__ void mma16816(float d[4], const uint32_t a[4], const uint32_t b[2]){
    asm volatile("mma.sync.aligned.m16n8k16.row.col.f32.bf16.bf16.f32 "
        "{%0,%1,%2,%3},{%4,%5,%6,%7},{%8,%9},{%0,%1,%2,%3};"
        : "+f"(d[0]),"+f"(d[1]),"+f"(d[2]),"+f"(d[3])
        : "r"(a[0]),"r"(a[1]),"r"(a[2]),"r"(a[3]),"r"(b[0]),"r"(b[1]));
}

#define GSMEM_TOTAL 196608   // 192 KB

// Copy [NROWS x 64 bf16] tile, rowbytes=128, XOR-(r&7) chunk swizzle. 256 thr.
template<int NROWS>
__device__ __forceinline__ void copy_rk(uint32_t dst, const __nv_bfloat16* src,
                                        int ld, int tid){
#pragma unroll
    for (int i=0;i<NROWS*8/256;i++){
        int idx = tid + i*256;
        int r = idx>>3, c = idx&7;
        uint32_t sw = (uint32_t)(r*128) + (uint32_t)(((c ^ (r&7))<<4));
        cp16(dst + sw, (const char*)src + ((long long)r*ld + c*8)*2);
    }
}
// Copy [64 rows(k) x NCOLS bf16(n)] tile, rowbytes=NCOLS*2, XOR swizzle.
template<int NCOLS>
__device__ __forceinline__ void copy_kn(uint32_t dst, const __nv_bfloat16* src,
                                        int ld, int tid){
    const int CPR = NCOLS/8;
#pragma unroll
    for (int i=0;i<64*CPR/256;i++){
        int idx = tid + i*256;
        int r = idx/CPR, c = idx%CPR;
        uint32_t sw = (uint32_t)(r*(NCOLS*2)) + (uint32_t)(((c ^ (r&7))<<4));
        cp16(dst + sw, (const char*)src + ((long long)r*ld + c*8)*2);
    }
}

// ----------------------------------------------------------------------------
// HMMA GEMM (R7-proven): C[M,N] = alpha*(Ah+Al)[M,K] @ (Bh+Bl)^T, fp32 acc.
// ----------------------------------------------------------------------------
template<int NT, bool BKN, bool CAUSAL, bool SPLITOUT, bool KTRUNC>
__global__ void __launch_bounds__(256) gemm_mma(
    const __nv_bfloat16* __restrict__ Ah, const __nv_bfloat16* __restrict__ Al,
    const __nv_bfloat16* __restrict__ Bh, const __nv_bfloat16* __restrict__ Bl,
    float* __restrict__ C,
    __nv_bfloat16* __restrict__ CH, __nv_bfloat16* __restrict__ CL,
    int K, int ldb, int ldc,
    long long sA, long long sB, long long sCo, long long sCi, int ndiv, float alpha)
{
    const int m0 = blockIdx.y*128, n0 = blockIdx.x*NT, z = blockIdx.z;
    if (CAUSAL && n0 > m0 + 127) return;
    const int NN8 = NT/32;
    const int TILEA = 16384;
    const int TILEBB = NT*128;
    const int STG = 2*TILEA + 2*TILEBB;
    const int NS = (NT==256) ? 2 : 3;

    extern __shared__ __align__(1024) char smem[];
    const uint32_t sb = smem_u32(smem);
    Ah += (long long)z*sA; Al += (long long)z*sA;
    Bh += (long long)z*sB; Bl += (long long)z*sB;
    long long coff = (long long)(z/ndiv)*sCo + (long long)(z%ndiv)*sCi;
    if (SPLITOUT){ CH += coff; CL += coff; } else { C += coff; }

    const int tid = threadIdx.x, lane = tid&31, wid = tid>>5;
    const int wm = wid>>2, wn = wid&3;

    float acc[4][NN8][4];
#pragma unroll
    for (int a=0;a<4;a++)
#pragma unroll
        for (int b=0;b<NN8;b++)
#pragma unroll
            for (int c=0;c<4;c++) acc[a][b][c] = 0.f;

    const int nch = KTRUNC ? ((m0+128)>>6) : (K>>6);

#define LOAD_CHUNK(cc, ss) do{ \
    uint32_t bbase = sb + (uint32_t)(ss)*STG; \
    copy_rk<128>(bbase,         Ah + (long long)m0*K + (cc)*64, K, tid); \
    copy_rk<128>(bbase + TILEA, Al + (long long)m0*K + (cc)*64, K, tid); \
    if (BKN){ \
        copy_kn<NT>(bbase + 2*TILEA,          Bh + (long long)(cc)*64*ldb + n0, ldb, tid); \
        copy_kn<NT>(bbase + 2*TILEA + TILEBB, Bl + (long long)(cc)*64*ldb + n0, ldb, tid); \
    } else { \
        copy_rk<NT>(bbase + 2*TILEA,          Bh + (long long)n0*K + (cc)*64, K, tid); \
        copy_rk<NT>(bbase + 2*TILEA + TILEBB, Bl + (long long)n0*K + (cc)*64, K, tid); \
    } \
    CP_COMMIT(); }while(0)

    LOAD_CHUNK(0, 0);
    if (NS > 1 && nch > 1) LOAD_CHUNK(1, 1);
    if (NS > 2 && nch > 2) LOAD_CHUNK(2, 2);

    const uint32_t axor = (uint32_t)(lane&7);

    for (int c=0; c<nch; c++){
        int pend = nch-1-c; if (pend > NS-1) pend = NS-1;
        if (pend >= 2) CP_WAIT(2);
        else if (pend == 1) CP_WAIT(1);
        else CP_WAIT(0);
        __syncthreads();
        uint32_t base = sb + (uint32_t)(c % NS)*STG;
#pragma unroll
        for (int ks=0; ks<4; ks++){
            uint32_t bh[NN8][2], bl[NN8][2];
#pragma unroll
            for (int nb=0;nb<NN8/2;nb++){
                uint32_t t[4];
                if (BKN){
                    uint32_t row = (uint32_t)(ks*16 + (lane&7) + (((lane>>3)&1)<<3));
                    uint32_t ch  = ((uint32_t)(wn*NN8 + nb*2 + (lane>>4)) ^ axor);
                    uint32_t ad  = base + 2*TILEA + row*(NT*2) + (ch<<4);
                    ldsm4t(t, ad);
                    bh[2*nb][0]=t[0]; bh[2*nb][1]=t[1]; bh[2*nb+1][0]=t[2]; bh[2*nb+1][1]=t[3];
                    ldsm4t(t, ad + TILEBB);
                    bl[2*nb][0]=t[0]; bl[2*nb][1]=t[1]; bl[2*nb+1][0]=t[2]; bl[2*nb+1][1]=t[3];
                } else {
                    uint32_t row = (uint32_t)(wn*(NT/4) + nb*16 + (lane&7) + ((lane>>4)<<3));
                    uint32_t ch  = ((uint32_t)(ks*2 + ((lane>>3)&1)) ^ axor);
                    uint32_t ad  = base + 2*TILEA + row*128 + (ch<<4);
                    ldsm4(t, ad);
                    bh[2*nb][0]=t[0]; bh[2*nb][1]=t[1]; bh[2*nb+1][0]=t[2]; bh[2*nb+1][1]=t[3];
                    ldsm4(t, ad + TILEBB);
                    bl[2*nb][0]=t[0]; bl[2*nb][1]=t[1]; bl[2*nb+1][0]=t[2]; bl[2*nb+1][1]=t[3];
                }
            }
#pragma unroll
            for (int mb=0;mb<4;mb++){
                uint32_t ah[4], al[4];
                uint32_t row = (uint32_t)(wm*64 + mb*16 + (lane&15));
                uint32_t col = (((uint32_t)(ks*2 + (lane>>4)) ^ (row&7u))<<4);
                uint32_t ad = base + row*128 + col;
                ldsm4(ah, ad);
                ldsm4(al, ad + TILEA);
#pragma unroll
                for (int n8=0;n8<NN8;n8++){
                    mma16816(acc[mb][n8], ah, bh[n8]);
                    mma16816(acc[mb][n8], ah, bl[n8]);
                    mma16816(acc[mb][n8], al, bh[n8]);
                }
            }
        }
        __syncthreads();
        if (c + NS < nch) LOAD_CHUNK(c + NS, c % NS);
    }
#undef LOAD_CHUNK

    // epilogue
#pragma unroll
    for (int mb=0;mb<4;mb++){
        int r0 = m0 + wm*64 + mb*16 + (lane>>2);
#pragma unroll
        for (int n8=0;n8<NN8;n8++){
            int cc = n0 + wn*(NT/4) + n8*8 + (lane&3)*2;
            float vx0 = acc[mb][n8][0]*alpha, vy0 = acc[mb][n8][1]*alpha;
            float vx1 = acc[mb][n8][2]*alpha, vy1 = acc[mb][n8][3]*alpha;
            if (SPLITOUT){
                __nv_bfloat162 h0, l0, h1, l1;
                h0.x = __float2bfloat16(vx0); h0.y = __float2bfloat16(vy0);
                l0.x = __float2bfloat16(vx0 - __bfloat162float(h0.x));
                l0.y = __float2bfloat16(vy0 - __bfloat162float(h0.y));
                h1.x = __float2bfloat16(vx1); h1.y = __float2bfloat16(vy1);
                l1.x = __float2bfloat16(vx1 - __bfloat162float(h1.x));
                l1.y = __float2bfloat16(vy1 - __bfloat162float(h1.y));
                *(__nv_bfloat162*)&CH[(long long)r0*ldc + cc] = h0;
                *(__nv_bfloat162*)&CL[(long long)r0*ldc + cc] = l0;
                *(__nv_bfloat162*)&CH[(long long)(r0+8)*ldc + cc] = h1;
                *(__nv_bfloat162*)&CL[(long long)(r0+8)*ldc + cc] = l1;
            } else {
                float2 v0; v0.x = vx0; v0.y = vy0;
                float2 v1; v1.x = vx1; v1.y = vy1;
                *(float2*)&C[(long long)r0*ldc + cc] = v0;
                *(float2*)&C[(long long)(r0+8)*ldc + cc] = v1;
            }
        }
    }
}

// ----------------------------------------------------------------------------
// fp32 -> bf16 hi/lo split (hs) and fused 4-weight variant
// ----------------------------------------------------------------------------
__device__ __forceinline__ void split_body(const float* __restrict__ X,
                                           __nv_bfloat16* __restrict__ H,
                                           __nv_bfloat16* __restrict__ L, int i)
{
    float4 v = *(const float4*)&X[i];
    __nv_bfloat16 h0=__float2bfloat16(v.x), h1=__float2bfloat16(v.y);
    __nv_bfloat16 h2=__float2bfloat16(v.z), h3=__float2bfloat16(v.w);
    __nv_bfloat162 H01; H01.x=h0; H01.y=h1;
    __nv_bfloat162 H23; H23.x=h2; H23.y=h3;
    *(__nv_bfloat162*)&H[i]   = H01;
    *(__nv_bfloat162*)&H[i+2] = H23;
    __nv_bfloat162 L01, L23;
    L01.x = __float2bfloat16(v.x - __bfloat162float(h0));
    L01.y = __float2bfloat16(v.y - __bfloat162float(h1));
    L23.x = __float2bfloat16(v.z - __bfloat162float(h2));
    L23.y = __float2bfloat16(v.w - __bfloat162float(h3));
    *(__nv_bfloat162*)&L[i]   = L01;
    *(__nv_bfloat162*)&L[i+2] = L23;
}

__global__ void split_plain(const float* __restrict__ X,
                            __nv_bfloat16* __restrict__ H,
                            __nv_bfloat16* __restrict__ L, int n)
{
    int i = (blockIdx.x*blockDim.x + threadIdx.x)*4;
    if (i < n) split_body(X, H, L, i);
}

__global__ void split_w4(const float* __restrict__ w0, const float* __restrict__ w1,
                         const float* __restrict__ w2, const float* __restrict__ w3,
                         __nv_bfloat16* __restrict__ H, __nv_bfloat16* __restrict__ L)
{
    const float* src = (blockIdx.y==0)?w0:(blockIdx.y==1)?w1:(blockIdx.y==2)?w2:w3;
    size_t off = (size_t)blockIdx.y * HIDc * HIDc;
    int i = (blockIdx.x*blockDim.x + threadIdx.x)*4;
    split_body(src, H + off, L + off, i);
}

// ----------------------------------------------------------------------------
// RoPE cos/sin tables + EMA weight table (fp64-accurate)
// ----------------------------------------------------------------------------
__global__ void rope_tables()
{
    int idx = blockIdx.x*blockDim.x + threadIdx.x;   // 0 .. Sc*64-1
    int s = idx >> 6, i = idx & 63;
    double inv = pow(10000.0, -(double)i/64.0);
    double a = (double)s * inv;
    g_tcos[idx] = (float)cos(a);
    g_tsin[idx] = (float)sin(a);
    if (idx < CBc) g_wcoef[idx] = (float)pow((double)FFc, (double)(CBc-1-idx));
}

// ----------------------------------------------------------------------------
// RoPE + [B,S,H*D]->[Z,S,D] layout + bf16 hi/lo split
// ----------------------------------------------------------------------------
__global__ void rope_split()
{
    long long idx = (long long)blockIdx.x * blockDim.x + threadIdx.x;
    if (idx >= (long long)NELT) return;

    int d = (int)(idx % HDc);
    int h = (int)((idx / HDc) % NHc);
    int s = (int)((idx / HIDc) % Sc);
    int b = (int)(idx / ((long long)Sc * HIDc));
    int z = b*NHc + h;

    long long lin = (long long)(b * Sc + s) * HIDc + h * HDc + d;
    long long out = (long long)(z * Sc + s) * HDc + d;

    const float* Qlin = g_lin;
    const float* Klin = g_lin + NELT;
    const float* Vlin = g_lin + 2*(long long)NELT;

    float q = Qlin[lin];
    float k = Klin[lin];
    float qr, kr;
    if (d < 64) { qr = -Qlin[lin + 64]; kr = -Klin[lin + 64]; }
    else        { qr =  Qlin[lin - 64]; kr =  Klin[lin - 64]; }

    int ti = (s<<6) + (d & 63);
    float c = g_tcos[ti], sn = g_tsin[ti];

    float qv = q * c + qr * sn;
    float kv = k * c + kr * sn;

    __nv_bfloat16 qh = __float2bfloat16(qv);
    g_QH[out] = qh; g_QL[out] = __float2bfloat16(qv - __bfloat162float(qh));
    __nv_bfloat16 kh = __float2bfloat16(kv);
    g_KH[out] = kh; g_KL[out] = __float2bfloat16(kv - __bfloat162float(kh));

    float vv = Vlin[lin];
    __nv_bfloat16 vh = __float2bfloat16(vv);
    g_VH[out] = vh; g_VL[out] = __float2bfloat16(vv - __bfloat162float(vh));
}

// ----------------------------------------------------------------------------
// Causal row softmax
// ----------------------------------------------------------------------------
__global__ void __launch_bounds__(256) softmax_causal(float* __restrict__ P)
{
    __shared__ float smA[9];
    __shared__ float smB[9];
    long long row = blockIdx.x;
    int r = (int)(row & (Sc-1));
    float* p = P + row * Sc;
    const int tid = threadIdx.x;
    const int lane = tid & 31, wid = tid >> 5;

    float v[4];
    float mx = -FLT_MAX;
#pragma unroll
    for (int i = 0; i < 4; i++) {
        int jj = tid + i*256;
        v[i] = (jj <= r) ? p[jj] : -FLT_MAX;
        mx = fmaxf(mx, v[i]);
    }
#pragma unroll
    for (int o = 16; o; o >>= 1) mx = fmaxf(mx, __shfl_xor_sync(0xffffffffu, mx, o));
    if (lane == 0) smA[wid] = mx;
    __syncthreads();
    if (tid < 8) {
        float x = smA[tid];
#pragma unroll
        for (int o = 4; o; o >>= 1) x = fmaxf(x, __shfl_xor_sync(0xffu, x, o));
        if (tid == 0) smA[8] = x;
    }
    __syncthreads();
    mx = smA[8];

    float sum = 0.f;
#pragma unroll
    for (int i = 0; i < 4; i++) { v[i] = expf(v[i] - mx); sum += v[i]; }
#pragma unroll
    for (int o = 16; o; o >>= 1) sum += __shfl_xor_sync(0xffffffffu, sum, o);
    if (lane == 0) smB[wid] = sum;
    __syncthreads();
    if (tid < 8) {
        float x = smB[tid];
#pragma unroll
        for (int o = 4; o; o >>= 1) x += __shfl_xor_sync(0xffu, x, o);
        if (tid == 0) smB[8] = x;
    }
    __syncthreads();
    sum = smB[8];

    float inv = 1.f / sum;
#pragma unroll
    for (int i = 0; i < 4; i++) p[tid + i * 256] = v[i] * inv;
}

// ----------------------------------------------------------------------------
// Sequential heavy-hitter eviction scan — 128 threads (4 warps), 8 cols/thread,
// ONE barrier per step. Each warp publishes (argmin key, next-row score at its
// candidate, next-row partial sum); total_{t+1} = Sum(partials) - score[mi].
// ----------------------------------------------------------------------------
__global__ void __launch_bounds__(128) scan_kernel(const float* __restrict__ P,
                                                   int* __restrict__ evict)
{
    const int z = blockIdx.x;
    const float* Pz = P + (long long)z * Sc * Sc;
    const int tid = threadIdx.x;
    const int lane = tid & 31, wid = tid >> 5;    // 4 warps
    const int j0 = tid * 8;
    const float INFV = __int_as_float(0x7f800000);

    __shared__ uint4 part[2][4];
    __shared__ float swc[CBc];

    for (int i = tid; i < CBc; i += 128) swc[i] = g_wcoef[i];
    __syncthreads();

    // EMA warmup over rows 0..CB-1
    float sel[8];
#pragma unroll
    for (int k=0;k<8;k++) sel[k] = 0.f;
#pragma unroll 4
    for (int i = 0; i < CBc; i++){
        float w = swc[i];
        float4 a = *(const float4*)&Pz[(long long)i*Sc + j0];
        float4 b = *(const float4*)&Pz[(long long)i*Sc + j0 + 4];
        sel[0] += w*a.x; sel[1] += w*a.y; sel[2] += w*a.z; sel[3] += w*a.w;
        sel[4] += w*b.x; sel[5] += w*b.y; sel[6] += w*b.z; sel[7] += w*b.w;
    }

    int e[8];
#pragma unroll
    for (int k=0;k<8;k++) e[k] = 0x7fffffff;

    // row buffers: scur=row t, snxt=row t+1, sfar=row t+2
    float scur[8], snxt[8], sfar[8];
    {
        float4 a, b;
        a = *(const float4*)&Pz[(long long)CBc*Sc + j0];
        b = *(const float4*)&Pz[(long long)CBc*Sc + j0 + 4];
        scur[0]=a.x;scur[1]=a.y;scur[2]=a.z;scur[3]=a.w;
        scur[4]=b.x;scur[5]=b.y;scur[6]=b.z;scur[7]=b.w;
        a = *(const float4*)&Pz[(long long)(CBc+1)*Sc + j0];
        b = *(const float4*)&Pz[(long long)(CBc+1)*Sc + j0 + 4];
        snxt[0]=a.x;snxt[1]=a.y;snxt[2]=a.z;snxt[3]=a.w;
        snxt[4]=b.x;snxt[5]=b.y;snxt[6]=b.z;snxt[7]=b.w;
        a = *(const float4*)&Pz[(long long)(CBc+2)*Sc + j0];
        b = *(const float4*)&Pz[(long long)(CBc+2)*Sc + j0 + 4];
        sfar[0]=a.x;sfar[1]=a.y;sfar[2]=a.z;sfar[3]=a.w;
        sfar[4]=b.x;sfar[5]=b.y;sfar[6]=b.z;sfar[7]=b.w;
    }

    // prologue: total for t=CB (all positions alive)
    float total;
    {
        float ps = 0.f;
#pragma unroll
        for (int k=0;k<8;k++) ps += scur[k];
#pragma unroll
        for (int o=16;o;o>>=1) ps += __shfl_xor_sync(0xffffffffu, ps, o);
        if (lane == 0) part[0][wid] = make_uint4(0u,0u,0u,__float_as_uint(ps));
        __syncthreads();
        total = 0.f;
#pragma unroll
        for (int w=0;w<4;w++) total += __uint_as_float(part[0][w].w);
    }

    for (int t = CBc; t <= Sc - 2; t++){
        const int par = t & 1;
        const float inv = 1.f / total;

        // sel update
#pragma unroll
        for (int k=0;k<8;k++){
            bool alive = (sel[k] < INFV);
            sel[k] = alive ? (FFc*sel[k] + scur[k]*inv) : INFV;
        }

        // thread-local window argmin (carry next-row score at candidate)
        const int hi = t - RBc;
        unsigned long long key = ~0ull;
        float scn = 0.f;
#pragma unroll
        for (int k=0;k<8;k++){
            int j = j0 + k;
            if (j >= SBc && j <= hi){
                unsigned long long kk =
                    (((unsigned long long)__float_as_uint(sel[k])) << 32) | (unsigned)j;
                if (kk < key){ key = kk; scn = snxt[k]; }
            }
        }
        // next-row partial sum over alive positions
        float ps = 0.f;
#pragma unroll
        for (int k=0;k<8;k++) if (sel[k] < INFV) ps += snxt[k];

        // warp reductions
#pragma unroll
        for (int o=16;o;o>>=1){
            unsigned long long ok = __shfl_xor_sync(0xffffffffu, key, o);
            float os = __shfl_xor_sync(0xffffffffu, scn, o);
            if (ok < key){ key = ok; scn = os; }
            ps += __shfl_xor_sync(0xffffffffu, ps, o);
        }
        if (lane == 0)
            part[par][wid] = make_uint4((uint32_t)key, (uint32_t)(key>>32),
                                        __float_as_uint(scn), __float_as_uint(ps));
        __syncthreads();

        // block reduce (redundant per thread)
        unsigned long long bk = ~0ull;
        float bscn = 0.f, raw = 0.f;
#pragma unroll
        for (int w=0;w<4;w++){
            uint4 q = part[par][w];
            unsigned long long k2 = (((unsigned long long)q.y)<<32) | q.x;
            if (k2 < bk){ bk = k2; bscn = __uint_as_float(q.z); }
            raw += __uint_as_float(q.w);
        }
        int mi = (int)(bk & 0xffffffffu);

        // evict
        if (mi >= j0 && mi < j0 + 8){
            sel[mi - j0] = INFV;
            e[mi - j0] = t;
        }
        total = raw - bscn;

        // rotate row buffers + prefetch row t+3
#pragma unroll
        for (int k=0;k<8;k++){ scur[k] = snxt[k]; snxt[k] = sfar[k]; }
        if (t + 3 <= Sc - 1){
            float4 a = *(const float4*)&Pz[(long long)(t+3)*Sc + j0];
            float4 b = *(const float4*)&Pz[(long long)(t+3)*Sc + j0 + 4];
            sfar[0]=a.x;sfar[1]=a.y;sfar[2]=a.z;sfar[3]=a.w;
            sfar[4]=b.x;sfar[5]=b.y;sfar[6]=b.z;sfar[7]=b.w;
        }
    }

#pragma unroll
    for (int k=0;k<8;k++) evict[z*Sc + j0 + k] = e[k];
}

// ----------------------------------------------------------------------------
// Keep-mask + renormalize; emit bf16 hi/lo splits
// ----------------------------------------------------------------------------
__global__ void __launch_bounds__(256) maskrenorm_split(const float* __restrict__ P,
                                                        const int* __restrict__ evict,
                                                        __nv_bfloat16* __restrict__ PH,
                                                        __nv_bfloat16* __restrict__ PL)
{
    __shared__ float smB[9];
    long long row = blockIdx.x;
    int z = (int)(row >> 10);
    int r = (int)(row & 1023);
    const float* p = P + row * Sc;
    const int* e = evict + z * Sc;
    const int tid = threadIdx.x;
    const int lane = tid & 31, wid = tid >> 5;

    float v[4];
    float sum = 0.f;
#pragma unroll
    for (int i = 0; i < 4; i++) {
        int jj = tid + i * 256;
        bool keep = (r <= CBc) || (e[jj] >= r);
        v[i] = keep ? p[jj] : 0.f;
        sum += v[i];
    }
#pragma unroll
    for (int o = 16; o; o >>= 1) sum += __shfl_xor_sync(0xffffffffu, sum, o);
    if (lane == 0) smB[wid] = sum;
    __syncthreads();
    if (tid < 8) {
        float x = smB[tid];
#pragma unroll
        for (int o = 4; o; o >>= 1) x += __shfl_xor_sync(0xffu, x, o);
        if (tid == 0) smB[8] = x;
    }
    __syncthreads();
    sum = smB[8];

    float inv = 1.f / sum;
    long long base = row * Sc;
#pragma unroll
    for (int i = 0; i < 4; i++) {
        int jj = tid + i * 256;
        float val = v[i] * inv;
        __nv_bfloat16 h = __float2bfloat16(val);
        PH[base + jj] = h;
        PL[base + jj] = __float2bfloat16(val - __bfloat162float(h));
    }
}

// ----------------------------------------------------------------------------
// Launch
// ----------------------------------------------------------------------------
extern "C" void kernel_launch(void* const* d_in, const int* in_sizes, int n_in,
                              void* d_out, int out_size)
{
    (void)in_sizes; (void)n_in; (void)out_size;
    const float* hs = (const float*)d_in[0];
    const float* wq = (const float*)d_in[1];
    const float* wk = (const float*)d_in[2];
    const float* wv = (const float*)d_in[3];
    const float* wo = (const float*)d_in[4];
    float* out = (float*)d_out;

    float *lin, *P;
    __nv_bfloat16 *hsH, *hsL, *wH, *wL;
    __nv_bfloat16 *QH, *QL, *KH, *KL, *VH, *VL, *PH, *PL, *cH, *cL;
    int* ev;
    cudaGetSymbolAddress((void**)&lin, g_lin);
    cudaGetSymbolAddress((void**)&hsH, g_hsH);  cudaGetSymbolAddress((void**)&hsL, g_hsL);
    cudaGetSymbolAddress((void**)&wH, g_wH);    cudaGetSymbolAddress((void**)&wL, g_wL);
    cudaGetSymbolAddress((void**)&QH, g_QH);    cudaGetSymbolAddress((void**)&QL, g_QL);
    cudaGetSymbolAddress((void**)&KH, g_KH);    cudaGetSymbolAddress((void**)&KL, g_KL);
    cudaGetSymbolAddress((void**)&VH, g_VH);    cudaGetSymbolAddress((void**)&VL, g_VL);
    cudaGetSymbolAddress((void**)&P, g_P);
    cudaGetSymbolAddress((void**)&PH, g_PH);    cudaGetSymbolAddress((void**)&PL, g_PL);
    cudaGetSymbolAddress((void**)&cH, g_cH);    cudaGetSymbolAddress((void**)&cL, g_cL);
    cudaGetSymbolAddress((void**)&ev, g_evict);

    cudaFuncSetAttribute((const void*)gemm_mma<256,true,false,false,false>,
                         cudaFuncAttributeMaxDynamicSharedMemorySize, GSMEM_TOTAL);
    cudaFuncSetAttribute((const void*)gemm_mma<256,false,true,false,false>,
                         cudaFuncAttributeMaxDynamicSharedMemorySize, GSMEM_TOTAL);
    cudaFuncSetAttribute((const void*)gemm_mma<128,true,false,true,true>,
                         cudaFuncAttributeMaxDynamicSharedMemorySize, GSMEM_TOTAL);

    const float qk_scale = 0.08838834764831845f;  // 1/sqrt(128)
    const int splitBlocks = NELT/4/256;

    // 0) tables (RoPE + EMA weights)
    rope_tables<<<(Sc*64)/256, 256>>>();

    // 1) bf16 hi/lo splits: hs + all 4 weights in one fused launch
    split_plain<<<splitBlocks, 256>>>(hs, hsH, hsL, NELT);
    split_w4<<<dim3(splitBlocks,4), 256>>>(wq, wk, wv, wo, wH, wL);

    // 2) Fused QKV projections (NT=256)
    gemm_mma<256,true,false,false,false><<<dim3(8,16,3), 256, GSMEM_TOTAL>>>(
        hsH, hsL, wH, wL, lin, nullptr, nullptr, HIDc, HIDc, HIDc,
        0, (long long)HIDc*HIDc, (long long)NELT, 0, 1, 1.f);

    // 3) RoPE + layout + split
    rope_split<<<NELT/256, 256>>>();

    // 4) QK^T causal, scaled (NT=256)
    gemm_mma<256,false,true,false,false><<<dim3(4,8,ZB), 256, GSMEM_TOTAL>>>(
        QH, QL, KH, KL, P, nullptr, nullptr, HDc, HDc, Sc,
        (long long)Sc*HDc, (long long)Sc*HDc,
        (long long)Sc*Sc, 0, 1, qk_scale);

    // 5) softmax
    softmax_causal<<<ZB*Sc, 256>>>(P);

    // 6) eviction scan (4 warps, 1 barrier/step)
    scan_kernel<<<ZB, 128>>>(P, ev);

    // 7) mask + renormalize -> bf16 splits
    maskrenorm_split<<<ZB*Sc, 256>>>(P, ev, PH, PL);

    // 8) PV -> ctx (NT=128, K truncated at diagonal, bf16 hi/lo out)
    gemm_mma<128,true,false,true,true><<<dim3(1,8,ZB), 256, GSMEM_TOTAL>>>(
        PH, PL, VH, VL, nullptr, cH, cL, Sc, HDc, HIDc,
        (long long)Sc*Sc, (long long)Sc*HDc,
        (long long)Sc*HIDc, (long long)HDc, NHc, 1.f);

    // 9) output projection (NT=256)
    gemm_mma<256,true,false,false,false><<<dim3(8,16,1), 256, GSMEM_TOTAL>>>(
        cH, cL, wH + 3*(size_t)HIDc*HIDc, wL + 3*(size_t)HIDc*HIDc, out,
        nullptr, nullptr, HIDc, HIDc, HIDc, 0, 0, 0, 0, 1, 1.f);
}

// round 9
// speedup vs baseline: 1.1946x; 1.0016x over previous
#include <cuda_runtime.h>
#include <cuda_bf16.h>
#include <math.h>
#include <float.h>
#include <stdint.h>

// Problem constants
#define Bc    2
#define Sc    1024
#define HIDc  2048
#define NHc   16
#define HDc   128
#define SBc   20
#define RBc   82
#define CBc   163
#define FFc   0.9f
#define BSc   (Bc*Sc)          // 2048
#define ZB    (Bc*NHc)         // 32
#define NELT  (BSc*HIDc)       // 4M

// ----------------------------------------------------------------------------
// Scratch
// ----------------------------------------------------------------------------
__device__ __align__(1024) float g_lin[3*NELT];                  // Q,K,V linear
__device__ __align__(1024) __nv_bfloat16 g_hsH[NELT];
__device__ __align__(1024) __nv_bfloat16 g_hsL[NELT];
__device__ __align__(1024) __nv_bfloat16 g_wH[4*HIDc*HIDc];      // wq,wk,wv,wo
__device__ __align__(1024) __nv_bfloat16 g_wL[4*HIDc*HIDc];
__device__ __align__(1024) __nv_bfloat16 g_QH[ZB*Sc*HDc];
__device__ __align__(1024) __nv_bfloat16 g_QL[ZB*Sc*HDc];
__device__ __align__(1024) __nv_bfloat16 g_KH[ZB*Sc*HDc];
__device__ __align__(1024) __nv_bfloat16 g_KL[ZB*Sc*HDc];
__device__ __align__(1024) __nv_bfloat16 g_VH[ZB*Sc*HDc];
__device__ __align__(1024) __nv_bfloat16 g_VL[ZB*Sc*HDc];
__device__ __align__(1024) float g_P[(size_t)ZB*Sc*Sc];
__device__ __align__(1024) __nv_bfloat16 g_PH[(size_t)ZB*Sc*Sc];
__device__ __align__(1024) __nv_bfloat16 g_PL[(size_t)ZB*Sc*Sc];
__device__ __align__(1024) __nv_bfloat16 g_cH[NELT];
__device__ __align__(1024) __nv_bfloat16 g_cL[NELT];
__device__ int g_evict[ZB*Sc];
__device__ float g_tcos[Sc*64];
__device__ float g_tsin[Sc*64];
__device__ float g_wcoef[CBc];

// ----------------------------------------------------------------------------
// PTX helpers
// ----------------------------------------------------------------------------
__device__ __forceinline__ uint32_t smem_u32(const void* p){
    uint32_t a;
    asm("{ .reg .u64 t; cvta.to.shared.u64 t, %1; cvt.u32.u64 %0, t; }":"=r"(a):"l"(p));
    return a;
}
__device__ __forceinline__ void cp16(uint32_t d, const void* s){
    asm volatile("cp.async.cg.shared.global [%0], [%1], 16;"::"r"(d),"l"(s));
}
#define CP_COMMIT() asm volatile("cp.async.commit_group;":::"memory")
#define CP_WAIT(n)  asm volatile("cp.async.wait_group %0;"::"n"(n):"memory")

__device__ __forceinline__ void ldsm4(uint32_t r[4], uint32_t a){
    asm volatile("ldmatrix.sync.aligned.m8n8.x4.shared.b16 {%0,%1,%2,%3}, [%4];"
        : "=r"(r[0]),"=r"(r[1]),"=r"(r[2]),"=r"(r[3]) : "r"(a));
}
__device__ __forceinline__ void ldsm4t(uint32_t r[4], uint32_t a){
    asm volatile("ldmatrix.sync.aligned.m8n8.x4.trans.shared.b16 {%0,%1,%2,%3}, [%4];"
        : "=r"(r[0]),"=r"(r[1]),"=r"(r[2]),"=r"(r[3]) : "r"(a));
}
__device__ __forceinline__ void mma16816(float d[4], const uint32_t a[4], const uint32_t b[2]){
    asm volatile("mma.sync.aligned.m16n8k16.row.col.f32.bf16.bf16.f32 "
        "{%0,%1,%2,%3},{%4,%5,%6,%7},{%8,%9},{%0,%1,%2,%3};"
        : "+f"(d[0]),"+f"(d[1]),"+f"(d[2]),"+f"(d[3])
        : "r"(a[0]),"r"(a[1]),"r"(a[2]),"r"(a[3]),"r"(b[0]),"r"(b[1]));
}

#define GSMEM_TOTAL 196608   // 192 KB

// Copy [NROWS x 64 bf16] tile, rowbytes=128, XOR-(r&7) chunk swizzle. 256 thr.
template<int NROWS>
__device__ __forceinline__ void copy_rk(uint32_t dst, const __nv_bfloat16* src,
                                        int ld, int tid){
#pragma unroll
    for (int i=0;i<NROWS*8/256;i++){
        int idx = tid + i*256;
        int r = idx>>3, c = idx&7;
        uint32_t sw = (uint32_t)(r*128) + (uint32_t)(((c ^ (r&7))<<4));
        cp16(dst + sw, (const char*)src + ((long long)r*ld + c*8)*2);
    }
}
// Copy [64 rows(k) x NCOLS bf16(n)] tile, rowbytes=NCOLS*2, XOR swizzle.
template<int NCOLS>
__device__ __forceinline__ void copy_kn(uint32_t dst, const __nv_bfloat16* src,
                                        int ld, int tid){
    const int CPR = NCOLS/8;
#pragma unroll
    for (int i=0;i<64*CPR/256;i++){
        int idx = tid + i*256;
        int r = idx/CPR, c = idx%CPR;
        uint32_t sw = (uint32_t)(r*(NCOLS*2)) + (uint32_t)(((c ^ (r&7))<<4));
        cp16(dst + sw, (const char*)src + ((long long)r*ld + c*8)*2);
    }
}

// ----------------------------------------------------------------------------
// HMMA GEMM: C[M,N] = alpha*(Ah+Al)[M,K] @ (Bh+Bl)^T, fp32 acc, 3-term split.
// Inner loop processes B in halves of 4 n8-groups to cap fragment live range
// (regs were pinned at 255 with spills in the NT=256 path).
// KTRUNC also reverses m0 (heavy PV blocks first).
// ----------------------------------------------------------------------------
template<int NT, bool BKN, bool CAUSAL, bool SPLITOUT, bool KTRUNC>
__global__ void __launch_bounds__(256) gemm_mma(
    const __nv_bfloat16* __restrict__ Ah, const __nv_bfloat16* __restrict__ Al,
    const __nv_bfloat16* __restrict__ Bh, const __nv_bfloat16* __restrict__ Bl,
    float* __restrict__ C,
    __nv_bfloat16* __restrict__ CH, __nv_bfloat16* __restrict__ CL,
    int K, int ldb, int ldc,
    long long sA, long long sB, long long sCo, long long sCi, int ndiv, float alpha)
{
    const int my = KTRUNC ? (gridDim.y - 1 - blockIdx.y) : blockIdx.y;
    const int m0 = my*128, n0 = blockIdx.x*NT, z = blockIdx.z;
    if (CAUSAL && n0 > m0 + 127) return;
    const int NN8 = NT/32;
    const int NHALF = NN8/4;          // 1 (NT=128) or 2 (NT=256)
    const int TILEA = 16384;
    const int TILEBB = NT*128;
    const int STG = 2*TILEA + 2*TILEBB;
    const int NS = (NT==256) ? 2 : 3;

    extern __shared__ __align__(1024) char smem[];
    const uint32_t sb = smem_u32(smem);
    Ah += (long long)z*sA; Al += (long long)z*sA;
    Bh += (long long)z*sB; Bl += (long long)z*sB;
    long long coff = (long long)(z/ndiv)*sCo + (long long)(z%ndiv)*sCi;
    if (SPLITOUT){ CH += coff; CL += coff; } else { C += coff; }

    const int tid = threadIdx.x, lane = tid&31, wid = tid>>5;
    const int wm = wid>>2, wn = wid&3;

    float acc[4][NN8][4];
#pragma unroll
    for (int a=0;a<4;a++)
#pragma unroll
        for (int b=0;b<NN8;b++)
#pragma unroll
            for (int c=0;c<4;c++) acc[a][b][c] = 0.f;

    const int nch = KTRUNC ? ((m0+128)>>6) : (K>>6);

#define LOAD_CHUNK(cc, ss) do{ \
    uint32_t bbase = sb + (uint32_t)(ss)*STG; \
    copy_rk<128>(bbase,         Ah + (long long)m0*K + (cc)*64, K, tid); \
    copy_rk<128>(bbase + TILEA, Al + (long long)m0*K + (cc)*64, K, tid); \
    if (BKN){ \
        copy_kn<NT>(bbase + 2*TILEA,          Bh + (long long)(cc)*64*ldb + n0, ldb, tid); \
        copy_kn<NT>(bbase + 2*TILEA + TILEBB, Bl + (long long)(cc)*64*ldb + n0, ldb, tid); \
    } else { \
        copy_rk<NT>(bbase + 2*TILEA,          Bh + (long long)n0*K + (cc)*64, K, tid); \
        copy_rk<NT>(bbase + 2*TILEA + TILEBB, Bl + (long long)n0*K + (cc)*64, K, tid); \
    } \
    CP_COMMIT(); }while(0)

    LOAD_CHUNK(0, 0);
    if (NS > 1 && nch > 1) LOAD_CHUNK(1, 1);
    if (NS > 2 && nch > 2) LOAD_CHUNK(2, 2);

    const uint32_t axor = (uint32_t)(lane&7);

    for (int c=0; c<nch; c++){
        int pend = nch-1-c; if (pend > NS-1) pend = NS-1;
        if (pend >= 2) CP_WAIT(2);
        else if (pend == 1) CP_WAIT(1);
        else CP_WAIT(0);
        __syncthreads();
        uint32_t base = sb + (uint32_t)(c % NS)*STG;
#pragma unroll
        for (int ks=0; ks<4; ks++){
#pragma unroll
            for (int half=0; half<NHALF; half++){
                uint32_t bh[4][2], bl[4][2];
#pragma unroll
                for (int nb=0;nb<2;nb++){
                    uint32_t t[4];
                    int gg = half*2 + nb;       // global pair index
                    if (BKN){
                        uint32_t row = (uint32_t)(ks*16 + (lane&7) + (((lane>>3)&1)<<3));
                        uint32_t ch  = ((uint32_t)(wn*NN8 + gg*2 + (lane>>4)) ^ axor);
                        uint32_t ad  = base + 2*TILEA + row*(NT*2) + (ch<<4);
                        ldsm4t(t, ad);
                        bh[2*nb][0]=t[0]; bh[2*nb][1]=t[1]; bh[2*nb+1][0]=t[2]; bh[2*nb+1][1]=t[3];
                        ldsm4t(t, ad + TILEBB);
                        bl[2*nb][0]=t[0]; bl[2*nb][1]=t[1]; bl[2*nb+1][0]=t[2]; bl[2*nb+1][1]=t[3];
                    } else {
                        uint32_t row = (uint32_t)(wn*(NT/4) + gg*16 + (lane&7) + ((lane>>4)<<3));
                        uint32_t ch  = ((uint32_t)(ks*2 + ((lane>>3)&1)) ^ axor);
                        uint32_t ad  = base + 2*TILEA + row*128 + (ch<<4);
                        ldsm4(t, ad);
                        bh[2*nb][0]=t[0]; bh[2*nb][1]=t[1]; bh[2*nb+1][0]=t[2]; bh[2*nb+1][1]=t[3];
                        ldsm4(t, ad + TILEBB);
                        bl[2*nb][0]=t[0]; bl[2*nb][1]=t[1]; bl[2*nb+1][0]=t[2]; bl[2*nb+1][1]=t[3];
                    }
                }
#pragma unroll
                for (int mb=0;mb<4;mb++){
                    uint32_t ah[4], al[4];
                    uint32_t row = (uint32_t)(wm*64 + mb*16 + (lane&15));
                    uint32_t col = (((uint32_t)(ks*2 + (lane>>4)) ^ (row&7u))<<4);
                    uint32_t ad = base + row*128 + col;
                    ldsm4(ah, ad);
                    ldsm4(al, ad + TILEA);
#pragma unroll
                    for (int n8=0;n8<4;n8++){
                        int g8 = half*4 + n8;
                        mma16816(acc[mb][g8], ah, bh[n8]);
                        mma16816(acc[mb][g8], ah, bl[n8]);
                        mma16816(acc[mb][g8], al, bh[n8]);
                    }
                }
            }
        }
        __syncthreads();
        if (c + NS < nch) LOAD_CHUNK(c + NS, c % NS);
    }
#undef LOAD_CHUNK

    // epilogue
#pragma unroll
    for (int mb=0;mb<4;mb++){
        int r0 = m0 + wm*64 + mb*16 + (lane>>2);
#pragma unroll
        for (int n8=0;n8<NN8;n8++){
            int cc = n0 + wn*(NT/4) + n8*8 + (lane&3)*2;
            float vx0 = acc[mb][n8][0]*alpha, vy0 = acc[mb][n8][1]*alpha;
            float vx1 = acc[mb][n8][2]*alpha, vy1 = acc[mb][n8][3]*alpha;
            if (SPLITOUT){
                __nv_bfloat162 h0, l0, h1, l1;
                h0.x = __float2bfloat16(vx0); h0.y = __float2bfloat16(vy0);
                l0.x = __float2bfloat16(vx0 - __bfloat162float(h0.x));
                l0.y = __float2bfloat16(vy0 - __bfloat162float(h0.y));
                h1.x = __float2bfloat16(vx1); h1.y = __float2bfloat16(vy1);
                l1.x = __float2bfloat16(vx1 - __bfloat162float(h1.x));
                l1.y = __float2bfloat16(vy1 - __bfloat162float(h1.y));
                *(__nv_bfloat162*)&CH[(long long)r0*ldc + cc] = h0;
                *(__nv_bfloat162*)&CL[(long long)r0*ldc + cc] = l0;
                *(__nv_bfloat162*)&CH[(long long)(r0+8)*ldc + cc] = h1;
                *(__nv_bfloat162*)&CL[(long long)(r0+8)*ldc + cc] = l1;
            } else {
                float2 v0; v0.x = vx0; v0.y = vy0;
                float2 v1; v1.x = vx1; v1.y = vy1;
                *(float2*)&C[(long long)r0*ldc + cc] = v0;
                *(float2*)&C[(long long)(r0+8)*ldc + cc] = v1;
            }
        }
    }
}

// ----------------------------------------------------------------------------
// fp32 -> bf16 hi/lo split (hs) and fused 4-weight variant
// ----------------------------------------------------------------------------
__device__ __forceinline__ void split_body(const float* __restrict__ X,
                                           __nv_bfloat16* __restrict__ H,
                                           __nv_bfloat16* __restrict__ L, int i)
{
    float4 v = *(const float4*)&X[i];
    __nv_bfloat16 h0=__float2bfloat16(v.x), h1=__float2bfloat16(v.y);
    __nv_bfloat16 h2=__float2bfloat16(v.z), h3=__float2bfloat16(v.w);
    __nv_bfloat162 H01; H01.x=h0; H01.y=h1;
    __nv_bfloat162 H23; H23.x=h2; H23.y=h3;
    *(__nv_bfloat162*)&H[i]   = H01;
    *(__nv_bfloat162*)&H[i+2] = H23;
    __nv_bfloat162 L01, L23;
    L01.x = __float2bfloat16(v.x - __bfloat162float(h0));
    L01.y = __float2bfloat16(v.y - __bfloat162float(h1));
    L23.x = __float2bfloat16(v.z - __bfloat162float(h2));
    L23.y = __float2bfloat16(v.w - __bfloat162float(h3));
    *(__nv_bfloat162*)&L[i]   = L01;
    *(__nv_bfloat162*)&L[i+2] = L23;
}

__global__ void split_plain(const float* __restrict__ X,
                            __nv_bfloat16* __restrict__ H,
                            __nv_bfloat16* __restrict__ L, int n)
{
    int i = (blockIdx.x*blockDim.x + threadIdx.x)*4;
    if (i < n) split_body(X, H, L, i);
}

__global__ void split_w4(const float* __restrict__ w0, const float* __restrict__ w1,
                         const float* __restrict__ w2, const float* __restrict__ w3,
                         __nv_bfloat16* __restrict__ H, __nv_bfloat16* __restrict__ L)
{
    const float* src = (blockIdx.y==0)?w0:(blockIdx.y==1)?w1:(blockIdx.y==2)?w2:w3;
    size_t off = (size_t)blockIdx.y * HIDc * HIDc;
    int i = (blockIdx.x*blockDim.x + threadIdx.x)*4;
    split_body(src, H + off, L + off, i);
}

// ----------------------------------------------------------------------------
// RoPE cos/sin tables + EMA weight table (fp64-accurate)
// ----------------------------------------------------------------------------
__global__ void rope_tables()
{
    int idx = blockIdx.x*blockDim.x + threadIdx.x;   // 0 .. Sc*64-1
    int s = idx >> 6, i = idx & 63;
    double inv = pow(10000.0, -(double)i/64.0);
    double a = (double)s * inv;
    g_tcos[idx] = (float)cos(a);
    g_tsin[idx] = (float)sin(a);
    if (idx < CBc) g_wcoef[idx] = (float)pow((double)FFc, (double)(CBc-1-idx));
}

// ----------------------------------------------------------------------------
// RoPE + [B,S,H*D]->[Z,S,D] layout + bf16 hi/lo split
// ----------------------------------------------------------------------------
__global__ void rope_split()
{
    long long idx = (long long)blockIdx.x * blockDim.x + threadIdx.x;
    if (idx >= (long long)NELT) return;

    int d = (int)(idx % HDc);
    int h = (int)((idx / HDc) % NHc);
    int s = (int)((idx / HIDc) % Sc);
    int b = (int)(idx / ((long long)Sc * HIDc));
    int z = b*NHc + h;

    long long lin = (long long)(b * Sc + s) * HIDc + h * HDc + d;
    long long out = (long long)(z * Sc + s) * HDc + d;

    const float* Qlin = g_lin;
    const float* Klin = g_lin + NELT;
    const float* Vlin = g_lin + 2*(long long)NELT;

    float q = Qlin[lin];
    float k = Klin[lin];
    float qr, kr;
    if (d < 64) { qr = -Qlin[lin + 64]; kr = -Klin[lin + 64]; }
    else        { qr =  Qlin[lin - 64]; kr =  Klin[lin - 64]; }

    int ti = (s<<6) + (d & 63);
    float c = g_tcos[ti], sn = g_tsin[ti];

    float qv = q * c + qr * sn;
    float kv = k * c + kr * sn;

    __nv_bfloat16 qh = __float2bfloat16(qv);
    g_QH[out] = qh; g_QL[out] = __float2bfloat16(qv - __bfloat162float(qh));
    __nv_bfloat16 kh = __float2bfloat16(kv);
    g_KH[out] = kh; g_KL[out] = __float2bfloat16(kv - __bfloat162float(kh));

    float vv = Vlin[lin];
    __nv_bfloat16 vh = __float2bfloat16(vv);
    g_VH[out] = vh; g_VL[out] = __float2bfloat16(vv - __bfloat162float(vh));
}

// ----------------------------------------------------------------------------
// Causal row softmax
// ----------------------------------------------------------------------------
__global__ void __launch_bounds__(256) softmax_causal(float* __restrict__ P)
{
    __shared__ float smA[9];
    __shared__ float smB[9];
    long long row = blockIdx.x;
    int r = (int)(row & (Sc-1));
    float* p = P + row * Sc;
    const int tid = threadIdx.x;
    const int lane = tid & 31, wid = tid >> 5;

    float v[4];
    float mx = -FLT_MAX;
#pragma unroll
    for (int i = 0; i < 4; i++) {
        int jj = tid + i*256;
        v[i] = (jj <= r) ? p[jj] : -FLT_MAX;
        mx = fmaxf(mx, v[i]);
    }
#pragma unroll
    for (int o = 16; o; o >>= 1) mx = fmaxf(mx, __shfl_xor_sync(0xffffffffu, mx, o));
    if (lane == 0) smA[wid] = mx;
    __syncthreads();
    if (tid < 8) {
        float x = smA[tid];
#pragma unroll
        for (int o = 4; o; o >>= 1) x = fmaxf(x, __shfl_xor_sync(0xffu, x, o));
        if (tid == 0) smA[8] = x;
    }
    __syncthreads();
    mx = smA[8];

    float sum = 0.f;
#pragma unroll
    for (int i = 0; i < 4; i++) { v[i] = expf(v[i] - mx); sum += v[i]; }
#pragma unroll
    for (int o = 16; o; o >>= 1) sum += __shfl_xor_sync(0xffffffffu, sum, o);
    if (lane == 0) smB[wid] = sum;
    __syncthreads();
    if (tid < 8) {
        float x = smB[tid];
#pragma unroll
        for (int o = 4; o; o >>= 1) x += __shfl_xor_sync(0xffu, x, o);
        if (tid == 0) smB[8] = x;
    }
    __syncthreads();
    sum = smB[8];

    float inv = 1.f / sum;
#pragma unroll
    for (int i = 0; i < 4; i++) p[tid + i * 256] = v[i] * inv;
}

// ----------------------------------------------------------------------------
// Sequential heavy-hitter eviction scan — 128 threads (4 warps), 8 cols/thread,
// ONE barrier per step (R8-proven).
// ----------------------------------------------------------------------------
__global__ void __launch_bounds__(128) scan_kernel(const float* __restrict__ P,
                                                   int* __restrict__ evict)
{
    const int z = blockIdx.x;
    const float* Pz = P + (long long)z * Sc * Sc;
    const int tid = threadIdx.x;
    const int lane = tid & 31, wid = tid >> 5;    // 4 warps
    const int j0 = tid * 8;
    const float INFV = __int_as_float(0x7f800000);

    __shared__ uint4 part[2][4];
    __shared__ float swc[CBc];

    for (int i = tid; i < CBc; i += 128) swc[i] = g_wcoef[i];
    __syncthreads();

    float sel[8];
#pragma unroll
    for (int k=0;k<8;k++) sel[k] = 0.f;
#pragma unroll 4
    for (int i = 0; i < CBc; i++){
        float w = swc[i];
        float4 a = *(const float4*)&Pz[(long long)i*Sc + j0];
        float4 b = *(const float4*)&Pz[(long long)i*Sc + j0 + 4];
        sel[0] += w*a.x; sel[1] += w*a.y; sel[2] += w*a.z; sel[3] += w*a.w;
        sel[4] += w*b.x; sel[5] += w*b.y; sel[6] += w*b.z; sel[7] += w*b.w;
    }

    int e[8];
#pragma unroll
    for (int k=0;k<8;k++) e[k] = 0x7fffffff;

    float scur[8], snxt[8], sfar[8];
    {
        float4 a, b;
        a = *(const float4*)&Pz[(long long)CBc*Sc + j0];
        b = *(const float4*)&Pz[(long long)CBc*Sc + j0 + 4];
        scur[0]=a.x;scur[1]=a.y;scur[2]=a.z;scur[3]=a.w;
        scur[4]=b.x;scur[5]=b.y;scur[6]=b.z;scur[7]=b.w;
        a = *(const float4*)&Pz[(long long)(CBc+1)*Sc + j0];
        b = *(const float4*)&Pz[(long long)(CBc+1)*Sc + j0 + 4];
        snxt[0]=a.x;snxt[1]=a.y;snxt[2]=a.z;snxt[3]=a.w;
        snxt[4]=b.x;snxt[5]=b.y;snxt[6]=b.z;snxt[7]=b.w;
        a = *(const float4*)&Pz[(long long)(CBc+2)*Sc + j0];
        b = *(const float4*)&Pz[(long long)(CBc+2)*Sc + j0 + 4];
        sfar[0]=a.x;sfar[1]=a.y;sfar[2]=a.z;sfar[3]=a.w;
        sfar[4]=b.x;sfar[5]=b.y;sfar[6]=b.z;sfar[7]=b.w;
    }

    float total;
    {
        float ps = 0.f;
#pragma unroll
        for (int k=0;k<8;k++) ps += scur[k];
#pragma unroll
        for (int o=16;o;o>>=1) ps += __shfl_xor_sync(0xffffffffu, ps, o);
        if (lane == 0) part[0][wid] = make_uint4(0u,0u,0u,__float_as_uint(ps));
        __syncthreads();
        total = 0.f;
#pragma unroll
        for (int w=0;w<4;w++) total += __uint_as_float(part[0][w].w);
    }

    for (int t = CBc; t <= Sc - 2; t++){
        const int par = t & 1;
        const float inv = 1.f / total;

#pragma unroll
        for (int k=0;k<8;k++){
            bool alive = (sel[k] < INFV);
            sel[k] = alive ? (FFc*sel[k] + scur[k]*inv) : INFV;
        }

        const int hi = t - RBc;
        unsigned long long key = ~0ull;
        float scn = 0.f;
#pragma unroll
        for (int k=0;k<8;k++){
            int j = j0 + k;
            if (j >= SBc && j <= hi){
                unsigned long long kk =
                    (((unsigned long long)__float_as_uint(sel[k])) << 32) | (unsigned)j;
                if (kk < key){ key = kk; scn = snxt[k]; }
            }
        }
        float ps = 0.f;
#pragma unroll
        for (int k=0;k<8;k++) if (sel[k] < INFV) ps += snxt[k];

#pragma unroll
        for (int o=16;o;o>>=1){
            unsigned long long ok = __shfl_xor_sync(0xffffffffu, key, o);
            float os = __shfl_xor_sync(0xffffffffu, scn, o);
            if (ok < key){ key = ok; scn = os; }
            ps += __shfl_xor_sync(0xffffffffu, ps, o);
        }
        if (lane == 0)
            part[par][wid] = make_uint4((uint32_t)key, (uint32_t)(key>>32),
                                        __float_as_uint(scn), __float_as_uint(ps));
        __syncthreads();

        unsigned long long bk = ~0ull;
        float bscn = 0.f, raw = 0.f;
#pragma unroll
        for (int w=0;w<4;w++){
            uint4 q = part[par][w];
            unsigned long long k2 = (((unsigned long long)q.y)<<32) | q.x;
            if (k2 < bk){ bk = k2; bscn = __uint_as_float(q.z); }
            raw += __uint_as_float(q.w);
        }
        int mi = (int)(bk & 0xffffffffu);

        if (mi >= j0 && mi < j0 + 8){
            sel[mi - j0] = INFV;
            e[mi - j0] = t;
        }
        total = raw - bscn;

#pragma unroll
        for (int k=0;k<8;k++){ scur[k] = snxt[k]; snxt[k] = sfar[k]; }
        if (t + 3 <= Sc - 1){
            float4 a = *(const float4*)&Pz[(long long)(t+3)*Sc + j0];
            float4 b = *(const float4*)&Pz[(long long)(t+3)*Sc + j0 + 4];
            sfar[0]=a.x;sfar[1]=a.y;sfar[2]=a.z;sfar[3]=a.w;
            sfar[4]=b.x;sfar[5]=b.y;sfar[6]=b.z;sfar[7]=b.w;
        }
    }

#pragma unroll
    for (int k=0;k<8;k++) evict[z*Sc + j0 + k] = e[k];
}

// ----------------------------------------------------------------------------
// Keep-mask + renormalize; emit bf16 hi/lo splits
// ----------------------------------------------------------------------------
__global__ void __launch_bounds__(256) maskrenorm_split(const float* __restrict__ P,
                                                        const int* __restrict__ evict,
                                                        __nv_bfloat16* __restrict__ PH,
                                                        __nv_bfloat16* __restrict__ PL)
{
    __shared__ float smB[9];
    long long row = blockIdx.x;
    int z = (int)(row >> 10);
    int r = (int)(row & 1023);
    const float* p = P + row * Sc;
    const int* e = evict + z * Sc;
    const int tid = threadIdx.x;
    const int lane = tid & 31, wid = tid >> 5;

    float v[4];
    float sum = 0.f;
#pragma unroll
    for (int i = 0; i < 4; i++) {
        int jj = tid + i * 256;
        bool keep = (r <= CBc) || (e[jj] >= r);
        v[i] = keep ? p[jj] : 0.f;
        sum += v[i];
    }
#pragma unroll
    for (int o = 16; o; o >>= 1) sum += __shfl_xor_sync(0xffffffffu, sum, o);
    if (lane == 0) smB[wid] = sum;
    __syncthreads();
    if (tid < 8) {
        float x = smB[tid];
#pragma unroll
        for (int o = 4; o; o >>= 1) x += __shfl_xor_sync(0xffu, x, o);
        if (tid == 0) smB[8] = x;
    }
    __syncthreads();
    sum = smB[8];

    float inv = 1.f / sum;
    long long base = row * Sc;
#pragma unroll
    for (int i = 0; i < 4; i++) {
        int jj = tid + i * 256;
        float val = v[i] * inv;
        __nv_bfloat16 h = __float2bfloat16(val);
        PH[base + jj] = h;
        PL[base + jj] = __float2bfloat16(val - __bfloat162float(h));
    }
}

// ----------------------------------------------------------------------------
// Launch
// ----------------------------------------------------------------------------
extern "C" void kernel_launch(void* const* d_in, const int* in_sizes, int n_in,
                              void* d_out, int out_size)
{
    (void)in_sizes; (void)n_in; (void)out_size;
    const float* hs = (const float*)d_in[0];
    const float* wq = (const float*)d_in[1];
    const float* wk = (const float*)d_in[2];
    const float* wv = (const float*)d_in[3];
    const float* wo = (const float*)d_in[4];
    float* out = (float*)d_out;

    float *lin, *P;
    __nv_bfloat16 *hsH, *hsL, *wH, *wL;
    __nv_bfloat16 *QH, *QL, *KH, *KL, *VH, *VL, *PH, *PL, *cH, *cL;
    int* ev;
    cudaGetSymbolAddress((void**)&lin, g_lin);
    cudaGetSymbolAddress((void**)&hsH, g_hsH);  cudaGetSymbolAddress((void**)&hsL, g_hsL);
    cudaGetSymbolAddress((void**)&wH, g_wH);    cudaGetSymbolAddress((void**)&wL, g_wL);
    cudaGetSymbolAddress((void**)&QH, g_QH);    cudaGetSymbolAddress((void**)&QL, g_QL);
    cudaGetSymbolAddress((void**)&KH, g_KH);    cudaGetSymbolAddress((void**)&KL, g_KL);
    cudaGetSymbolAddress((void**)&VH, g_VH);    cudaGetSymbolAddress((void**)&VL, g_VL);
    cudaGetSymbolAddress((void**)&P, g_P);
    cudaGetSymbolAddress((void**)&PH, g_PH);    cudaGetSymbolAddress((void**)&PL, g_PL);
    cudaGetSymbolAddress((void**)&cH, g_cH);    cudaGetSymbolAddress((void**)&cL, g_cL);
    cudaGetSymbolAddress((void**)&ev, g_evict);

    cudaFuncSetAttribute((const void*)gemm_mma<256,true,false,false,false>,
                         cudaFuncAttributeMaxDynamicSharedMemorySize, GSMEM_TOTAL);
    cudaFuncSetAttribute((const void*)gemm_mma<256,false,true,false,false>,
                         cudaFuncAttributeMaxDynamicSharedMemorySize, GSMEM_TOTAL);
    cudaFuncSetAttribute((const void*)gemm_mma<128,true,false,true,true>,
                         cudaFuncAttributeMaxDynamicSharedMemorySize, GSMEM_TOTAL);

    const float qk_scale = 0.08838834764831845f;  // 1/sqrt(128)
    const int splitBlocks = NELT/4/256;

    // 0) tables (RoPE + EMA weights)
    rope_tables<<<(Sc*64)/256, 256>>>();

    // 1) bf16 hi/lo splits: hs + all 4 weights in one fused launch
    split_plain<<<splitBlocks, 256>>>(hs, hsH, hsL, NELT);
    split_w4<<<dim3(splitBlocks,4), 256>>>(wq, wk, wv, wo, wH, wL);

    // 2) Fused QKV projections (NT=256)
    gemm_mma<256,true,false,false,false><<<dim3(8,16,3), 256, GSMEM_TOTAL>>>(
        hsH, hsL, wH, wL, lin, nullptr, nullptr, HIDc, HIDc, HIDc,
        0, (long long)HIDc*HIDc, (long long)NELT, 0, 1, 1.f);

    // 3) RoPE + layout + split
    rope_split<<<NELT/256, 256>>>();

    // 4) QK^T causal, scaled (NT=256)
    gemm_mma<256,false,true,false,false><<<dim3(4,8,ZB), 256, GSMEM_TOTAL>>>(
        QH, QL, KH, KL, P, nullptr, nullptr, HDc, HDc, Sc,
        (long long)Sc*HDc, (long long)Sc*HDc,
        (long long)Sc*Sc, 0, 1, qk_scale);

    // 5) softmax
    softmax_causal<<<ZB*Sc, 256>>>(P);

    // 6) eviction scan (4 warps, 1 barrier/step)
    scan_kernel<<<ZB, 128>>>(P, ev);

    // 7) mask + renormalize -> bf16 splits
    maskrenorm_split<<<ZB*Sc, 256>>>(P, ev, PH, PL);

    // 8) PV -> ctx (NT=128, K truncated at diagonal, heavy-first, bf16 out)
    gemm_mma<128,true,false,true,true><<<dim3(1,8,ZB), 256, GSMEM_TOTAL>>>(
        PH, PL, VH, VL, nullptr, cH, cL, Sc, HDc, HIDc,
        (long long)Sc*Sc, (long long)Sc*HDc,
        (long long)Sc*HIDc, (long long)HDc, NHc, 1.f);

    // 9) output projection (NT=256)
    gemm_mma<256,true,false,false,false><<<dim3(8,16,1), 256, GSMEM_TOTAL>>>(
        cH, cL, wH + 3*(size_t)HIDc*HIDc, wL + 3*(size_t)HIDc*HIDc, out,
        nullptr, nullptr, HIDc, HIDc, HIDc, 0, 0, 0, 0, 1, 1.f);
}